// round 4
// baseline (speedup 1.0000x reference)
#include <cuda_runtime.h>
#include <math.h>

#define NHEADS   4
#define WIN      7
#define NTOK     49
#define CDIM     128
#define C3       384
#define NWIN     64
#define NBLK     2048
#define NTHREADS 512
#define PSTRIDE  52

typedef unsigned long long u64;

__device__ __forceinline__ void ffma2(u64 &d, u64 a, u64 b) {
    asm("fma.rn.f32x2 %0, %1, %2, %3;" : "=l"(d) : "l"(a), "l"(b), "l"(d));
}
__device__ __forceinline__ u64 dup2(float x) {
    u64 r; asm("mov.b64 %0, {%1, %1};" : "=l"(r) : "f"(x)); return r;
}
__device__ __forceinline__ float2 unpack2(u64 v) {
    float2 r; asm("mov.b64 {%0, %1}, %2;" : "=f"(r.x), "=f"(r.y) : "l"(v)); return r;
}

// smem (floats): xs[49*128] | q_s[49*128] | k_s[49*128] | v_s[52*128] | p_s[4*49*52]
#define XS_F   (NTOK * CDIM)           // 6272
#define V_F    (52 * CDIM)             // 6656 (rows 49..51 zero)
#define PS_F   (NHEADS * NTOK * PSTRIDE)
#define SMEM_FLOATS (3 * XS_F + V_F + PS_F)
#define SMEM_BYTES  (SMEM_FLOATS * sizeof(float))

__device__ float g_comb[NWIN * NHEADS * NTOK * NTOK];   // bias + mask precombined

__global__ void swin_comb_kernel(const float* __restrict__ rel_table,
                                 const float* __restrict__ mask) {
    int e = blockIdx.x * blockDim.x + threadIdx.x;
    if (e >= NWIN * NHEADS * NTOK * NTOK) return;
    int j = e % NTOK;
    int t = e / NTOK;
    int i = t % NTOK;  t /= NTOK;
    int h = t % NHEADS;
    int w = t / NHEADS;
    int yi = i / WIN, xi = i % WIN, yj = j / WIN, xj = j % WIN;
    int r = (yi - yj + WIN - 1) * (2 * WIN - 1) + (xi - xj + WIN - 1);
    g_comb[e] = rel_table[r * NHEADS + h] + mask[(w * NTOK + i) * NTOK + j];
}

__global__ __launch_bounds__(NTHREADS, 1)
void swin_attn_kernel(const float* __restrict__ x_g,
                      const float* __restrict__ qkv_w,
                      const float* __restrict__ qkv_b,
                      const float* __restrict__ proj_w,
                      const float* __restrict__ proj_b,
                      float* __restrict__ out_g) {
    const int blk  = blockIdx.x;
    const int wi   = blk & (NWIN - 1);
    const int tid  = threadIdx.x;
    const int lane = tid & 31;
    const int warp = tid >> 5;

    extern __shared__ float smem[];
    float* xs  = smem;                       // x, later O
    float* q_s = smem + XS_F;
    float* k_s = smem + 2 * XS_F;            // swizzled (float4-XOR by row&7)
    float* v_s = smem + 3 * XS_F;            // plain, 52 rows (49..51 zero)
    float* p_s = smem + 3 * XS_F + V_F;      // [4][49][52], cols 49..51 zero

    float4* xs4 = reinterpret_cast<float4*>(xs);
    float4* q4  = reinterpret_cast<float4*>(q_s);
    float4* k4  = reinterpret_cast<float4*>(k_s);
    float4* v4  = reinterpret_cast<float4*>(v_s);

    // ---- stage 1: load x + zero-fill padding ----
    {
        const float4* xin = reinterpret_cast<const float4*>(x_g + (size_t)blk * (NTOK * CDIM));
        for (int o = tid; o < (NTOK * CDIM) / 4; o += NTHREADS) xs4[o] = xin[o];
        if (tid < 96) v4[49 * 32 + tid] = make_float4(0.f, 0.f, 0.f, 0.f);  // V rows 49..51
        for (int o = tid; o < NHEADS * NTOK * 3; o += NTHREADS) {           // P cols 49..51
            int rr = o / 3, cc = o % 3;
            p_s[rr * PSTRIDE + 49 + cc] = 0.f;
        }
    }
    __syncthreads();

    // ---- stage 2: qkv = x @ qkv_w + qkv_b ----
    // 16 warps = 2 col-halves (192 cols) x 8 row-groups (7 rows, start 6*rg; overlaps benign)
    {
        const int ch = warp & 1;
        const int rg = warp >> 1;
        const int rbase = rg * 6;             // rows rbase..rbase+6 (max 48)

        u64 acc[7][3];
        #pragma unroll
        for (int t = 0; t < 7; t++) { acc[t][0] = 0ull; acc[t][1] = 0ull; acc[t][2] = 0ull; }

        const float2* wp2 = reinterpret_cast<const float2*>(qkv_w) + ch * 96 + lane; // row stride 192 f2

        #pragma unroll 2
        for (int k4i = 0; k4i < 32; k4i++) {
            float2 w[4][3];
            #pragma unroll
            for (int kk = 0; kk < 4; kk++) {
                const float2* wr = wp2 + (size_t)(4 * k4i + kk) * 192;
                w[kk][0] = wr[0]; w[kk][1] = wr[32]; w[kk][2] = wr[64];
            }
            #pragma unroll
            for (int t = 0; t < 7; t++) {
                float4 a4 = xs4[(rbase + t) * 32 + k4i];       // broadcast
                float av[4] = {a4.x, a4.y, a4.z, a4.w};
                #pragma unroll
                for (int kk = 0; kk < 4; kk++) {
                    u64 ad = dup2(av[kk]);
                    #pragma unroll
                    for (int c = 0; c < 3; c++)
                        ffma2(acc[t][c], ad, *reinterpret_cast<const u64*>(&w[kk][c]));
                }
            }
        }

        float2 b2[3];
        {
            const float2* bv = reinterpret_cast<const float2*>(qkv_b) + ch * 96 + lane;
            b2[0] = bv[0]; b2[1] = bv[32]; b2[2] = bv[64];
        }
        #pragma unroll
        for (int t = 0; t < 7; t++) {
            int r = rbase + t;
            #pragma unroll
            for (int c = 0; c < 3; c++) {
                int cc   = ch * 3 + c;        // 64-col chunk id 0..5
                int dest = cc >> 1;           // 0=Q 1=K 2=V
                int half = cc & 1;
                float2 p = unpack2(acc[t][c]);
                float2 o = make_float2(p.x + b2[c].x, p.y + b2[c].y);
                if (dest == 0) {
                    *reinterpret_cast<float2*>(&q_s[r * 128 + half * 64 + 2 * lane]) = o;
                } else if (dest == 1) {
                    int f4 = (half * 16 + (lane >> 1)) ^ (r & 7);
                    *reinterpret_cast<float2*>(&k_s[r * 128 + f4 * 4 + (lane & 1) * 2]) = o;
                } else {
                    *reinterpret_cast<float2*>(&v_s[r * 128 + half * 64 + 2 * lane]) = o;
                }
            }
        }
    }
    __syncthreads();

    // ---- stage 3: logits (d-pair packed) + softmax -> p_s ----
    {
        const float scale = 0.17677669529663687f;   // 1/sqrt(32)
        const int j1 = lane;
        const int j2 = lane + 32;
        const int j2c = (j2 < NTOK) ? j2 : (NTOK - 1);
        const bool vld2 = (j2 < NTOK);

        for (int grp = warp; grp < 28; grp += 16) {
            const int h  = grp / 7;
            const int i0 = (grp % 7) * 7;            // exact: 7 groups x 7 i's = 49
            const int hb = h * 8;

            u64 acc[7][2];
            #pragma unroll
            for (int ii = 0; ii < 7; ii++) { acc[ii][0] = 0ull; acc[ii][1] = 0ull; }

            #pragma unroll
            for (int d4 = 0; d4 < 8; d4++) {
                float4 k1v = k4[j1  * 32 + ((hb + d4) ^ (j1  & 7))];
                float4 k2v = k4[j2c * 32 + ((hb + d4) ^ (j2c & 7))];
                const u64* k1p = reinterpret_cast<const u64*>(&k1v);
                const u64* k2p = reinterpret_cast<const u64*>(&k2v);
                #pragma unroll
                for (int ii = 0; ii < 7; ii++) {
                    float4 qv = q4[(i0 + ii) * 32 + hb + d4];   // broadcast
                    const u64* qp = reinterpret_cast<const u64*>(&qv);
                    ffma2(acc[ii][0], qp[0], k1p[0]);
                    ffma2(acc[ii][0], qp[1], k1p[1]);
                    ffma2(acc[ii][1], qp[0], k2p[0]);
                    ffma2(acc[ii][1], qp[1], k2p[1]);
                }
            }

            #pragma unroll
            for (int ii = 0; ii < 7; ii++) {
                int i = i0 + ii;
                float2 a0 = unpack2(acc[ii][0]);
                float2 a1 = unpack2(acc[ii][1]);
                float s1 = a0.x + a0.y;
                float s2 = a1.x + a1.y;
                const float* comb = g_comb + ((size_t)((wi * NHEADS + h) * NTOK + i)) * NTOK;
                s1 = fmaf(s1, scale, comb[j1]);
                float s2f = fmaf(s2, scale, comb[j2c]);
                s2 = vld2 ? s2f : -INFINITY;

                float m = fmaxf(s1, s2);
                #pragma unroll
                for (int off = 16; off; off >>= 1) m = fmaxf(m, __shfl_xor_sync(0xffffffffu, m, off));
                float e1 = __expf(s1 - m);
                float e2 = vld2 ? __expf(s2 - m) : 0.f;
                float sum = e1 + e2;
                #pragma unroll
                for (int off = 16; off; off >>= 1) sum += __shfl_xor_sync(0xffffffffu, sum, off);
                float inv = 1.0f / sum;

                float* prow = p_s + (h * NTOK + i) * PSTRIDE;
                prow[j1] = e1 * inv;
                if (vld2) prow[j2] = e2 * inv;
            }
        }
    }
    __syncthreads();

    // ---- stage 5: O = P @ V -> xs (16 warps x 4 tokens; duplicates benign) ----
    {
        const int h  = lane >> 3;            // head of this lane's 4 channels
        int i0 = 4 * warp; if (i0 > 45) i0 = 45;

        u64 acc[4][2];
        #pragma unroll
        for (int ii = 0; ii < 4; ii++) { acc[ii][0] = 0ull; acc[ii][1] = 0ull; }

        #pragma unroll 4
        for (int j4 = 0; j4 < 13; j4++) {
            float4 pv[4];
            #pragma unroll
            for (int ii = 0; ii < 4; ii++)
                pv[ii] = reinterpret_cast<const float4*>(p_s + (h * NTOK + i0 + ii) * PSTRIDE)[j4];
            #pragma unroll
            for (int jj = 0; jj < 4; jj++) {
                int j = j4 * 4 + jj;
                float4 vv = v4[j * 32 + lane];
                const u64* vp = reinterpret_cast<const u64*>(&vv);
                u64 d0 = dup2((&pv[0].x)[jj]);
                u64 d1 = dup2((&pv[1].x)[jj]);
                u64 d2 = dup2((&pv[2].x)[jj]);
                u64 d3 = dup2((&pv[3].x)[jj]);
                ffma2(acc[0][0], d0, vp[0]); ffma2(acc[0][1], d0, vp[1]);
                ffma2(acc[1][0], d1, vp[0]); ffma2(acc[1][1], d1, vp[1]);
                ffma2(acc[2][0], d2, vp[0]); ffma2(acc[2][1], d2, vp[1]);
                ffma2(acc[3][0], d3, vp[0]); ffma2(acc[3][1], d3, vp[1]);
            }
        }
        __syncthreads();   // all p/v reads done before xs overwrite? xs != p/v, safe; sync for x->O reuse
        #pragma unroll
        for (int ii = 0; ii < 4; ii++) {
            float2 p0 = unpack2(acc[ii][0]);
            float2 p1 = unpack2(acc[ii][1]);
            xs4[(i0 + ii) * 32 + lane] = make_float4(p0.x, p0.y, p1.x, p1.y);
        }
    }
    __syncthreads();

    // ---- stage 6: out = O @ proj_w + proj_b (2 col-halves x 8 row-groups of 7) ----
    {
        const int ch = warp & 1;
        const int rg = warp >> 1;
        const int rbase = rg * 6;

        u64 acc[7];
        #pragma unroll
        for (int t = 0; t < 7; t++) acc[t] = 0ull;

        const float2* wp2 = reinterpret_cast<const float2*>(proj_w) + ch * 32 + lane; // row stride 64 f2

        #pragma unroll 2
        for (int k4i = 0; k4i < 32; k4i++) {
            float2 w[4];
            #pragma unroll
            for (int kk = 0; kk < 4; kk++) w[kk] = wp2[(size_t)(4 * k4i + kk) * 64];
            #pragma unroll
            for (int t = 0; t < 7; t++) {
                float4 a4 = xs4[(rbase + t) * 32 + k4i];    // broadcast (O)
                float av[4] = {a4.x, a4.y, a4.z, a4.w};
                #pragma unroll
                for (int kk = 0; kk < 4; kk++)
                    ffma2(acc[t], dup2(av[kk]), *reinterpret_cast<const u64*>(&w[kk]));
            }
        }

        float2 b2 = reinterpret_cast<const float2*>(proj_b)[ch * 32 + lane];
        float* outp = out_g + (size_t)blk * (NTOK * CDIM);
        #pragma unroll
        for (int t = 0; t < 7; t++) {
            int r = rbase + t;
            float2 p = unpack2(acc[t]);
            *reinterpret_cast<float2*>(&outp[r * 128 + ch * 64 + 2 * lane]) =
                make_float2(p.x + b2.x, p.y + b2.y);
        }
    }
}

extern "C" void kernel_launch(void* const* d_in, const int* in_sizes, int n_in,
                              void* d_out, int out_size) {
    const float* x      = (const float*)d_in[0];
    const float* mask   = (const float*)d_in[1];
    const float* qkv_w  = (const float*)d_in[2];
    const float* qkv_b  = (const float*)d_in[3];
    const float* proj_w = (const float*)d_in[4];
    const float* proj_b = (const float*)d_in[5];
    const float* rel    = (const float*)d_in[6];
    float* out = (float*)d_out;

    (void)in_sizes; (void)n_in; (void)out_size;

    cudaFuncSetAttribute(swin_attn_kernel,
                         cudaFuncAttributeMaxDynamicSharedMemorySize, SMEM_BYTES);

    int ncomb = NWIN * NHEADS * NTOK * NTOK;
    swin_comb_kernel<<<(ncomb + 255) / 256, 256>>>(rel, mask);
    swin_attn_kernel<<<NBLK, NTHREADS, SMEM_BYTES>>>(x, qkv_w, qkv_b,
                                                     proj_w, proj_b, out);
}

// round 7
// speedup vs baseline: 1.2259x; 1.2259x over previous
#include <cuda_runtime.h>
#include <cuda_bf16.h>
#include <math.h>
#include <stdint.h>

#define NHEADS   4
#define WIN      7
#define NTOK     49
#define CDIM     128
#define NWIN     64
#define NBLK     2048
#define NTHREADS 512
#define PSTR     52

typedef unsigned long long u64;

// ---------------- packed fp32 helpers ----------------
__device__ __forceinline__ void ffma2(u64 &d, u64 a, u64 b) {
    asm("fma.rn.f32x2 %0, %1, %2, %3;" : "=l"(d) : "l"(a), "l"(b), "l"(d));
}
__device__ __forceinline__ u64 dup2(float x) {
    u64 r; asm("mov.b64 %0, {%1, %1};" : "=l"(r) : "f"(x)); return r;
}
__device__ __forceinline__ float2 unpack2(u64 v) {
    float2 r; asm("mov.b64 {%0, %1}, %2;" : "=f"(r.x), "=f"(r.y) : "l"(v)); return r;
}

// ---------------- mma.sync helpers (sm_80+, valid on base sm_100) ----------------
__device__ __forceinline__ uint32_t smem_u32(const void* p) {
    uint32_t a;
    asm("{ .reg .u64 t; cvta.to.shared.u64 t, %1; cvt.u32.u64 %0, t; }" : "=r"(a) : "l"(p));
    return a;
}
__device__ __forceinline__ void ldmx4(uint32_t* d, uint32_t addr) {
    asm volatile("ldmatrix.sync.aligned.m8n8.x4.shared.b16 {%0,%1,%2,%3}, [%4];"
        : "=r"(d[0]), "=r"(d[1]), "=r"(d[2]), "=r"(d[3]) : "r"(addr));
}
__device__ __forceinline__ void mma16816(float* c, const uint32_t* a, uint32_t b0, uint32_t b1) {
    asm volatile("mma.sync.aligned.m16n8k16.row.col.f32.bf16.bf16.f32 "
        "{%0,%1,%2,%3}, {%4,%5,%6,%7}, {%8,%9}, {%0,%1,%2,%3};"
        : "+f"(c[0]), "+f"(c[1]), "+f"(c[2]), "+f"(c[3])
        : "r"(a[0]), "r"(a[1]), "r"(a[2]), "r"(a[3]), "r"(b0), "r"(b1));
}

// ---------------- smem layout (bytes) ----------------
// A images: 64 rows x 136 bf16 (stride 272B, 17x16B -> ldmatrix conflict-free)
#define AROW_B    272
#define A_HI_B    0
#define A_LO_B    17408
#define B_HI_B    34816        // B chunk: 128 rows x 272B
#define B_LO_B    69632
#define Q_B       104448       // 49 rows x 132 floats
#define K_B       130320
#define V_B       156192       // 52 rows x 132 floats (49..51 zero)
#define P_B       183648       // [4][49][52] floats (cols 49..51 zero)
#define SMEM_TOTAL_B 224416

// ---------------- device globals ----------------
__device__ float g_comb[NWIN * NHEADS * NTOK * NTOK];
// Bt images: [chunk][split][n 128][k 136] bf16 (one chunk = 69632B contiguous)
__device__ unsigned short g_Bqkv[3 * 2 * 128 * 136];
__device__ unsigned short g_Bproj[2 * 128 * 136];

__global__ void swin_comb_kernel(const float* __restrict__ rel_table,
                                 const float* __restrict__ mask) {
    int e = blockIdx.x * blockDim.x + threadIdx.x;
    if (e >= NWIN * NHEADS * NTOK * NTOK) return;
    int j = e % NTOK;
    int t = e / NTOK;
    int i = t % NTOK;  t /= NTOK;
    int h = t % NHEADS;
    int w = t / NHEADS;
    int yi = i / WIN, xi = i % WIN, yj = j / WIN, xj = j % WIN;
    int r = (yi - yj + WIN - 1) * (2 * WIN - 1) + (xi - xj + WIN - 1);
    g_comb[e] = rel_table[r * NHEADS + h] + mask[(w * NTOK + i) * NTOK + j];
}

__global__ void swin_split_kernel(const float* __restrict__ qkv_w,
                                  const float* __restrict__ proj_w) {
    int e = blockIdx.x * blockDim.x + threadIdx.x;
    if (e < 384 * 128) {
        int k = e / 384, col = e % 384;
        float w = qkv_w[k * 384 + col];
        __nv_bfloat16 hi = __float2bfloat16(w);
        __nv_bfloat16 lo = __float2bfloat16(w - __bfloat162float(hi));
        int chunk = col >> 7, n = col & 127;
        g_Bqkv[((chunk * 2 + 0) * 128 + n) * 136 + k] = __bfloat16_as_ushort(hi);
        g_Bqkv[((chunk * 2 + 1) * 128 + n) * 136 + k] = __bfloat16_as_ushort(lo);
    } else if (e < 384 * 128 + 128 * 128) {
        int e2 = e - 384 * 128;
        int k = e2 / 128, n = e2 % 128;
        float w = proj_w[k * 128 + n];
        __nv_bfloat16 hi = __float2bfloat16(w);
        __nv_bfloat16 lo = __float2bfloat16(w - __bfloat162float(hi));
        g_Bproj[(0 * 128 + n) * 136 + k] = __bfloat16_as_ushort(hi);
        g_Bproj[(1 * 128 + n) * 136 + k] = __bfloat16_as_ushort(lo);
    }
}

__device__ __forceinline__ void split2(float x0, float x1, uint32_t &hp, uint32_t &lp) {
    __nv_bfloat16 h0 = __float2bfloat16(x0);
    __nv_bfloat16 h1 = __float2bfloat16(x1);
    __nv_bfloat16 l0 = __float2bfloat16(x0 - __bfloat162float(h0));
    __nv_bfloat16 l1 = __float2bfloat16(x1 - __bfloat162float(h1));
    hp = ((uint32_t)__bfloat16_as_ushort(h1) << 16) | __bfloat16_as_ushort(h0);
    lp = ((uint32_t)__bfloat16_as_ushort(l1) << 16) | __bfloat16_as_ushort(l0);
}

__global__ __launch_bounds__(NTHREADS, 1)
void swin_mma_kernel(const float* __restrict__ x_g,
                     const float* __restrict__ qkv_b,
                     const float* __restrict__ proj_b,
                     float* __restrict__ out_g) {
    const int blk  = blockIdx.x;          // one window
    const int wi   = blk & (NWIN - 1);
    const int tid  = threadIdx.x;
    const int lane = tid & 31;
    const int warp = tid >> 5;

    extern __shared__ float smem[];
    char* smb = reinterpret_cast<char*>(smem);
    const uint32_t smem_base = smem_u32(smem);

    // ---- phase 1a: x -> A hi/lo bf16 images; zero pads ----
    {
        const float2* xin = reinterpret_cast<const float2*>(x_g + (size_t)blk * (NTOK * CDIM));
        for (int e = tid; e < NTOK * 64; e += NTHREADS) {
            int row = e >> 6, kp = e & 63;
            float2 v = xin[e];
            uint32_t hp, lp; split2(v.x, v.y, hp, lp);
            uint32_t o = (uint32_t)row * AROW_B + kp * 4;
            *reinterpret_cast<uint32_t*>(smb + A_HI_B + o) = hp;
            *reinterpret_cast<uint32_t*>(smb + A_LO_B + o) = lp;
        }
        // zero A rows 49..63 (both images): 15 rows x 17 float4 x 2
        for (int o = tid; o < 510; o += NTHREADS) {
            int img = o / 255, rem = o % 255;
            int rr = rem / 17, c = rem % 17;
            *reinterpret_cast<float4*>(smb + img * 17408 + (49 + rr) * AROW_B + c * 16) =
                make_float4(0.f, 0.f, 0.f, 0.f);
        }
        // zero V pad rows 49..51 (3 x 33 float4)
        for (int o = tid; o < 99; o += NTHREADS) {
            *reinterpret_cast<float4*>(smb + V_B + (49 + o / 33) * 528 + (o % 33) * 16) =
                make_float4(0.f, 0.f, 0.f, 0.f);
        }
        // zero P pad cols 49..51
        float* ps = reinterpret_cast<float*>(smb + P_B);
        for (int o = tid; o < NHEADS * NTOK * 3; o += NTHREADS)
            ps[(o / 3) * PSTR + 49 + (o % 3)] = 0.f;
    }
    __syncthreads();

    const int mt = warp & 3;              // M tile (16 rows)
    const int ng = warp >> 2;             // N group (32 cols)

    // ---- phase 1b: load A fragments (held across all QKV chunks) ----
    uint32_t a_hi[8][4], a_lo[8][4];
    {
        uint32_t ra = smem_base + (mt * 16 + (lane & 15)) * AROW_B + (lane >> 4) * 16;
        #pragma unroll
        for (int k = 0; k < 8; k++) {
            ldmx4(a_hi[k], ra + A_HI_B + k * 32);
            ldmx4(a_lo[k], ra + A_LO_B + k * 32);
        }
    }

    // ---- phase 1c: QKV GEMM, 3 chunks of 128 cols ----
    for (int chunk = 0; chunk < 3; chunk++) {
        const float4* src = reinterpret_cast<const float4*>(g_Bqkv) + chunk * 4352;
        float4* dst = reinterpret_cast<float4*>(smb + B_HI_B);
        for (int o = tid; o < 4352; o += NTHREADS) dst[o] = src[o];
        __syncthreads();

        float* qkvdst = reinterpret_cast<float*>(smb + (chunk == 0 ? Q_B : chunk == 1 ? K_B : V_B));
        const int r1 = mt * 16 + (lane >> 2);
        const int r2 = r1 + 8;

        #pragma unroll
        for (int nt = 0; nt < 4; nt++) {
            const int n0 = ng * 32 + nt * 8;
            float c[4] = {0.f, 0.f, 0.f, 0.f};
            uint32_t bad = smem_base + B_HI_B + (n0 + (lane & 7)) * AROW_B + ((lane >> 3) & 3) * 16;
            #pragma unroll
            for (int kt2 = 0; kt2 < 4; kt2++) {
                uint32_t bh[4], bl[4];
                ldmx4(bh, bad + kt2 * 64);
                ldmx4(bl, bad + 34816 + kt2 * 64);
                mma16816(c, a_hi[2 * kt2],     bh[0], bh[1]);
                mma16816(c, a_hi[2 * kt2],     bl[0], bl[1]);
                mma16816(c, a_lo[2 * kt2],     bh[0], bh[1]);
                mma16816(c, a_hi[2 * kt2 + 1], bh[2], bh[3]);
                mma16816(c, a_hi[2 * kt2 + 1], bl[2], bl[3]);
                mma16816(c, a_lo[2 * kt2 + 1], bh[2], bh[3]);
            }
            int coll = n0 + 2 * (lane & 3);
            float2 bias = __ldg(reinterpret_cast<const float2*>(qkv_b + chunk * 128 + coll));
            if (r1 < NTOK)
                *reinterpret_cast<float2*>(qkvdst + r1 * 132 + coll) =
                    make_float2(c[0] + bias.x, c[1] + bias.y);
            if (r2 < NTOK)
                *reinterpret_cast<float2*>(qkvdst + r2 * 132 + coll) =
                    make_float2(c[2] + bias.x, c[3] + bias.y);
        }
        __syncthreads();
    }

    // ---- phase 2: attention (fp32 FFMA2) ----
    float4* q4 = reinterpret_cast<float4*>(smb + Q_B);
    float4* k4 = reinterpret_cast<float4*>(smb + K_B);
    float4* v4 = reinterpret_cast<float4*>(smb + V_B);
    float*  ps = reinterpret_cast<float*>(smb + P_B);
    float4* p4 = reinterpret_cast<float4*>(smb + P_B);

    // stage 3: logits + softmax -> P
    {
        const float scale = 0.17677669529663687f;   // 1/sqrt(32)
        const int j1 = lane;
        const int j2 = lane + 32;
        const int j2c = (j2 < NTOK) ? j2 : (NTOK - 1);
        const bool vld2 = (j2 < NTOK);

        for (int grp = warp; grp < 28; grp += 16) {
            const int h  = grp / 7;
            const int i0 = (grp % 7) * 7;
            const int hb = h * 8;

            u64 acc[7][2];
            #pragma unroll
            for (int ii = 0; ii < 7; ii++) { acc[ii][0] = 0ull; acc[ii][1] = 0ull; }

            #pragma unroll
            for (int d4 = 0; d4 < 8; d4++) {
                float4 k1v = k4[j1  * 33 + hb + d4];
                float4 k2v = k4[j2c * 33 + hb + d4];
                const u64* k1p = reinterpret_cast<const u64*>(&k1v);
                const u64* k2p = reinterpret_cast<const u64*>(&k2v);
                #pragma unroll
                for (int ii = 0; ii < 7; ii++) {
                    float4 qv = q4[(i0 + ii) * 33 + hb + d4];
                    const u64* qp = reinterpret_cast<const u64*>(&qv);
                    ffma2(acc[ii][0], qp[0], k1p[0]);
                    ffma2(acc[ii][0], qp[1], k1p[1]);
                    ffma2(acc[ii][1], qp[0], k2p[0]);
                    ffma2(acc[ii][1], qp[1], k2p[1]);
                }
            }
            #pragma unroll
            for (int ii = 0; ii < 7; ii++) {
                int i = i0 + ii;
                float2 a0 = unpack2(acc[ii][0]);
                float2 a1 = unpack2(acc[ii][1]);
                float s1 = a0.x + a0.y;
                float s2 = a1.x + a1.y;
                const float* comb = g_comb + ((size_t)((wi * NHEADS + h) * NTOK + i)) * NTOK;
                s1 = fmaf(s1, scale, comb[j1]);
                float s2f = fmaf(s2, scale, comb[j2c]);
                s2 = vld2 ? s2f : -INFINITY;

                float m = fmaxf(s1, s2);
                #pragma unroll
                for (int off = 16; off; off >>= 1) m = fmaxf(m, __shfl_xor_sync(0xffffffffu, m, off));
                float e1 = __expf(s1 - m);
                float e2 = vld2 ? __expf(s2 - m) : 0.f;
                float sum = e1 + e2;
                #pragma unroll
                for (int off = 16; off; off >>= 1) sum += __shfl_xor_sync(0xffffffffu, sum, off);
                float inv = 1.0f / sum;

                float* prow = ps + (h * NTOK + i) * PSTR;
                prow[j1] = e1 * inv;
                if (vld2) prow[j2] = e2 * inv;
            }
        }
    }
    __syncthreads();

    // stage 5: O = P @ V -> Q region (overwrite)
    {
        const int h = lane >> 3;
        int i0 = 4 * warp; if (i0 > 45) i0 = 45;

        u64 acc[4][2];
        #pragma unroll
        for (int ii = 0; ii < 4; ii++) { acc[ii][0] = 0ull; acc[ii][1] = 0ull; }

        #pragma unroll 4
        for (int j4 = 0; j4 < 13; j4++) {
            float4 pv[4];
            #pragma unroll
            for (int ii = 0; ii < 4; ii++)
                pv[ii] = p4[(h * NTOK + i0 + ii) * 13 + j4];
            #pragma unroll
            for (int jj = 0; jj < 4; jj++) {
                int j = 4 * j4 + jj;
                float4 vv = v4[j * 33 + lane];
                const u64* vp = reinterpret_cast<const u64*>(&vv);
                u64 d0 = dup2((&pv[0].x)[jj]);
                u64 d1 = dup2((&pv[1].x)[jj]);
                u64 d2 = dup2((&pv[2].x)[jj]);
                u64 d3 = dup2((&pv[3].x)[jj]);
                ffma2(acc[0][0], d0, vp[0]); ffma2(acc[0][1], d0, vp[1]);
                ffma2(acc[1][0], d1, vp[0]); ffma2(acc[1][1], d1, vp[1]);
                ffma2(acc[2][0], d2, vp[0]); ffma2(acc[2][1], d2, vp[1]);
                ffma2(acc[3][0], d3, vp[0]); ffma2(acc[3][1], d3, vp[1]);
            }
        }
        #pragma unroll
        for (int ii = 0; ii < 4; ii++) {
            float2 p0 = unpack2(acc[ii][0]);
            float2 p1 = unpack2(acc[ii][1]);
            q4[(i0 + ii) * 33 + lane] = make_float4(p0.x, p0.y, p1.x, p1.y);
        }
    }
    __syncthreads();

    // ---- phase 3: proj via mma ----
    {
        // O (Q region) -> A' images (A region reused; pad rows still zero)
        const float* op = reinterpret_cast<const float*>(smb + Q_B);
        for (int e = tid; e < NTOK * 64; e += NTHREADS) {
            int row = e >> 6, kp = e & 63;
            float x0 = op[row * 132 + 2 * kp];
            float x1 = op[row * 132 + 2 * kp + 1];
            uint32_t hp, lp; split2(x0, x1, hp, lp);
            uint32_t o = (uint32_t)row * AROW_B + kp * 4;
            *reinterpret_cast<uint32_t*>(smb + A_HI_B + o) = hp;
            *reinterpret_cast<uint32_t*>(smb + A_LO_B + o) = lp;
        }
        // stage proj B
        const float4* src = reinterpret_cast<const float4*>(g_Bproj);
        float4* dst = reinterpret_cast<float4*>(smb + B_HI_B);
        for (int o = tid; o < 4352; o += NTHREADS) dst[o] = src[o];
        __syncthreads();

        uint32_t ra = smem_base + (mt * 16 + (lane & 15)) * AROW_B + (lane >> 4) * 16;
        uint32_t b_hi2[8][4], b_lo2[8][4];   // reuse names: A' frags
        #pragma unroll
        for (int k = 0; k < 8; k++) {
            ldmx4(b_hi2[k], ra + A_HI_B + k * 32);
            ldmx4(b_lo2[k], ra + A_LO_B + k * 32);
        }

        const int r1 = mt * 16 + (lane >> 2);
        const int r2 = r1 + 8;
        float* outp = out_g + (size_t)blk * (NTOK * CDIM);

        #pragma unroll
        for (int nt = 0; nt < 4; nt++) {
            const int n0 = ng * 32 + nt * 8;
            float c[4] = {0.f, 0.f, 0.f, 0.f};
            uint32_t bad = smem_base + B_HI_B + (n0 + (lane & 7)) * AROW_B + ((lane >> 3) & 3) * 16;
            #pragma unroll
            for (int kt2 = 0; kt2 < 4; kt2++) {
                uint32_t bh[4], bl[4];
                ldmx4(bh, bad + kt2 * 64);
                ldmx4(bl, bad + 34816 + kt2 * 64);
                mma16816(c, b_hi2[2 * kt2],     bh[0], bh[1]);
                mma16816(c, b_hi2[2 * kt2],     bl[0], bl[1]);
                mma16816(c, b_lo2[2 * kt2],     bh[0], bh[1]);
                mma16816(c, b_hi2[2 * kt2 + 1], bh[2], bh[3]);
                mma16816(c, b_hi2[2 * kt2 + 1], bl[2], bl[3]);
                mma16816(c, b_lo2[2 * kt2 + 1], bh[2], bh[3]);
            }
            int coll = n0 + 2 * (lane & 3);
            float2 bias = __ldg(reinterpret_cast<const float2*>(proj_b + coll));
            if (r1 < NTOK)
                *reinterpret_cast<float2*>(outp + r1 * CDIM + coll) =
                    make_float2(c[0] + bias.x, c[1] + bias.y);
            if (r2 < NTOK)
                *reinterpret_cast<float2*>(outp + r2 * CDIM + coll) =
                    make_float2(c[2] + bias.x, c[3] + bias.y);
        }
    }
}

extern "C" void kernel_launch(void* const* d_in, const int* in_sizes, int n_in,
                              void* d_out, int out_size) {
    const float* x      = (const float*)d_in[0];
    const float* mask   = (const float*)d_in[1];
    const float* qkv_w  = (const float*)d_in[2];
    const float* qkv_b  = (const float*)d_in[3];
    const float* proj_w = (const float*)d_in[4];
    const float* proj_b = (const float*)d_in[5];
    const float* rel    = (const float*)d_in[6];
    float* out = (float*)d_out;

    (void)in_sizes; (void)n_in; (void)out_size;

    cudaFuncSetAttribute(swin_mma_kernel,
                         cudaFuncAttributeMaxDynamicSharedMemorySize, SMEM_TOTAL_B);

    int ncomb = NWIN * NHEADS * NTOK * NTOK;
    swin_comb_kernel<<<(ncomb + 255) / 256, 256>>>(rel, mask);
    int nsplit = 384 * 128 + 128 * 128;
    swin_split_kernel<<<(nsplit + 255) / 256, 256>>>(qkv_w, proj_w);
    swin_mma_kernel<<<NBLK, NTHREADS, SMEM_TOTAL_B>>>(x, qkv_b, proj_b, out);
}

// round 8
// speedup vs baseline: 1.4424x; 1.1765x over previous
#include <cuda_runtime.h>
#include <cuda_bf16.h>
#include <math.h>
#include <stdint.h>

#define NHEADS   4
#define WIN      7
#define NTOK     49
#define CDIM     128
#define NWIN     64
#define NBLK     2048
#define NTHREADS 512
#define PSTR     52

typedef unsigned long long u64;

// ---------------- packed fp32 helpers ----------------
__device__ __forceinline__ void ffma2(u64 &d, u64 a, u64 b) {
    asm("fma.rn.f32x2 %0, %1, %2, %3;" : "=l"(d) : "l"(a), "l"(b), "l"(d));
}
__device__ __forceinline__ u64 dup2(float x) {
    u64 r; asm("mov.b64 %0, {%1, %1};" : "=l"(r) : "f"(x)); return r;
}
__device__ __forceinline__ float2 unpack2(u64 v) {
    float2 r; asm("mov.b64 {%0, %1}, %2;" : "=f"(r.x), "=f"(r.y) : "l"(v)); return r;
}

// ---------------- mma.sync helpers ----------------
__device__ __forceinline__ uint32_t smem_u32(const void* p) {
    uint32_t a;
    asm("{ .reg .u64 t; cvta.to.shared.u64 t, %1; cvt.u32.u64 %0, t; }" : "=r"(a) : "l"(p));
    return a;
}
__device__ __forceinline__ void ldmx4(uint32_t* d, uint32_t addr) {
    asm volatile("ldmatrix.sync.aligned.m8n8.x4.shared.b16 {%0,%1,%2,%3}, [%4];"
        : "=r"(d[0]), "=r"(d[1]), "=r"(d[2]), "=r"(d[3]) : "r"(addr));
}
__device__ __forceinline__ void mma16816(float* c, const uint32_t* a, uint32_t b0, uint32_t b1) {
    asm volatile("mma.sync.aligned.m16n8k16.row.col.f32.bf16.bf16.f32 "
        "{%0,%1,%2,%3}, {%4,%5,%6,%7}, {%8,%9}, {%0,%1,%2,%3};"
        : "+f"(c[0]), "+f"(c[1]), "+f"(c[2]), "+f"(c[3])
        : "r"(a[0]), "r"(a[1]), "r"(a[2]), "r"(a[3]), "r"(b0), "r"(b1));
}

// ---------------- smem layout (bytes) ----------------
#define AROW_B    272          // 136 bf16 per row, ldmatrix conflict-free
#define A_HI_B    0
#define A_LO_B    17408
#define Q_B       34816        // 49 rows x 132 floats
#define K_B       60688
#define V_B       86560        // 52 rows x 132 floats (49..51 zero)
#define P_B       114016       // [4][49][52] floats (cols 49..51 zero)
#define SMEM_TOTAL_B 154784

// ---------------- device globals ----------------
__device__ float g_comb[NWIN * NHEADS * NTOK * NTOK];
// fragment-ordered weight images: idx = ((((chunk*4+ng)*4+nt)*4+kt2)*2+img)*32+lane
// uint4 per lane = regs m0..m3; value pair (k, k+1) bf16, k = kt2*32+m*8+2*(lane&3),
// n = ng*32+nt*8+(lane>>2)
__device__ uint4 g_BqkvF[12288];    // 3 chunks -> 192KB
__device__ uint4 g_BprojF[4096];    // 64KB

__global__ void swin_comb_kernel(const float* __restrict__ rel_table,
                                 const float* __restrict__ mask) {
    int e = blockIdx.x * blockDim.x + threadIdx.x;
    if (e >= NWIN * NHEADS * NTOK * NTOK) return;
    int j = e % NTOK;
    int t = e / NTOK;
    int i = t % NTOK;  t /= NTOK;
    int h = t % NHEADS;
    int w = t / NHEADS;
    int yi = i / WIN, xi = i % WIN, yj = j / WIN, xj = j % WIN;
    int r = (yi - yj + WIN - 1) * (2 * WIN - 1) + (xi - xj + WIN - 1);
    g_comb[e] = rel_table[r * NHEADS + h] + mask[(w * NTOK + i) * NTOK + j];
}

__device__ __forceinline__ uint32_t pack_split(float w0, float w1, int img) {
    __nv_bfloat16 h0 = __float2bfloat16(w0);
    __nv_bfloat16 h1 = __float2bfloat16(w1);
    if (img == 0)
        return ((uint32_t)__bfloat16_as_ushort(h1) << 16) | __bfloat16_as_ushort(h0);
    __nv_bfloat16 l0 = __float2bfloat16(w0 - __bfloat162float(h0));
    __nv_bfloat16 l1 = __float2bfloat16(w1 - __bfloat162float(h1));
    return ((uint32_t)__bfloat16_as_ushort(l1) << 16) | __bfloat16_as_ushort(l0);
}

__global__ void swin_split_kernel(const float* __restrict__ qkv_w,
                                  const float* __restrict__ proj_w) {
    int e = blockIdx.x * blockDim.x + threadIdx.x;
    if (e >= 16384) return;
    bool isproj = (e >= 12288);
    int idx = isproj ? (e - 12288) : e;
    int lane = idx & 31;
    int img  = (idx >> 5) & 1;
    int kt2  = (idx >> 6) & 3;
    int nt   = (idx >> 8) & 3;
    int ng   = (idx >> 10) & 3;
    int chunk = isproj ? 0 : (idx >> 12);
    int n = ng * 32 + nt * 8 + (lane >> 2);
    uint32_t r[4];
    #pragma unroll
    for (int m = 0; m < 4; m++) {
        int k = kt2 * 32 + m * 8 + 2 * (lane & 3);
        float w0, w1;
        if (isproj) { w0 = proj_w[k * 128 + n];                w1 = proj_w[(k + 1) * 128 + n]; }
        else        { w0 = qkv_w[k * 384 + chunk * 128 + n];   w1 = qkv_w[(k + 1) * 384 + chunk * 128 + n]; }
        r[m] = pack_split(w0, w1, img);
    }
    uint4 v = make_uint4(r[0], r[1], r[2], r[3]);
    if (isproj) g_BprojF[idx] = v; else g_BqkvF[idx] = v;
}

__device__ __forceinline__ void split2(float x0, float x1, uint32_t &hp, uint32_t &lp) {
    __nv_bfloat16 h0 = __float2bfloat16(x0);
    __nv_bfloat16 h1 = __float2bfloat16(x1);
    __nv_bfloat16 l0 = __float2bfloat16(x0 - __bfloat162float(h0));
    __nv_bfloat16 l1 = __float2bfloat16(x1 - __bfloat162float(h1));
    hp = ((uint32_t)__bfloat16_as_ushort(h1) << 16) | __bfloat16_as_ushort(h0);
    lp = ((uint32_t)__bfloat16_as_ushort(l1) << 16) | __bfloat16_as_ushort(l0);
}

__global__ __launch_bounds__(NTHREADS, 1)
void swin_mma_kernel(const float* __restrict__ x_g,
                     const float* __restrict__ qkv_b,
                     const float* __restrict__ proj_b,
                     float* __restrict__ out_g) {
    const int blk  = blockIdx.x;
    const int wi   = blk & (NWIN - 1);
    const int tid  = threadIdx.x;
    const int lane = tid & 31;
    const int warp = tid >> 5;

    extern __shared__ float smem[];
    char* smb = reinterpret_cast<char*>(smem);
    const uint32_t smem_base = smem_u32(smem);

    // ---- phase 1a: x -> A hi/lo bf16 images; zero pads ----
    {
        const float2* xin = reinterpret_cast<const float2*>(x_g + (size_t)blk * (NTOK * CDIM));
        for (int e = tid; e < NTOK * 64; e += NTHREADS) {
            int row = e >> 6, kp = e & 63;
            float2 v = xin[e];
            uint32_t hp, lp; split2(v.x, v.y, hp, lp);
            uint32_t o = (uint32_t)row * AROW_B + kp * 4;
            *reinterpret_cast<uint32_t*>(smb + A_HI_B + o) = hp;
            *reinterpret_cast<uint32_t*>(smb + A_LO_B + o) = lp;
        }
        // zero A rows 49..63 (both images)
        for (int o = tid; o < 510; o += NTHREADS) {
            int img = o / 255, rem = o % 255;
            int rr = rem / 17, c = rem % 17;
            *reinterpret_cast<float4*>(smb + img * 17408 + (49 + rr) * AROW_B + c * 16) =
                make_float4(0.f, 0.f, 0.f, 0.f);
        }
        // zero V pad rows 49..51
        for (int o = tid; o < 99; o += NTHREADS) {
            *reinterpret_cast<float4*>(smb + V_B + (49 + o / 33) * 528 + (o % 33) * 16) =
                make_float4(0.f, 0.f, 0.f, 0.f);
        }
        // zero P pad cols 49..51
        float* ps = reinterpret_cast<float*>(smb + P_B);
        for (int o = tid; o < NHEADS * NTOK * 3; o += NTHREADS)
            ps[(o / 3) * PSTR + 49 + (o % 3)] = 0.f;
    }
    __syncthreads();

    const int mt = warp & 3;              // M tile (16 rows)
    const int ng = warp >> 2;             // N group (32 cols)

    // ---- phase 1b: load A fragments (held across all QKV chunks) ----
    uint32_t a_hi[8][4], a_lo[8][4];
    {
        uint32_t ra = smem_base + (mt * 16 + (lane & 15)) * AROW_B + (lane >> 4) * 16;
        #pragma unroll
        for (int k = 0; k < 8; k++) {
            ldmx4(a_hi[k], ra + A_HI_B + k * 32);
            ldmx4(a_lo[k], ra + A_LO_B + k * 32);
        }
    }

    // ---- phase 1c: QKV GEMM, 3 chunks, fragment-direct B from global ----
    const int r1 = mt * 16 + (lane >> 2);
    const int r2 = r1 + 8;
    #pragma unroll
    for (int chunk = 0; chunk < 3; chunk++) {
        float* qkvdst = reinterpret_cast<float*>(smb + (chunk == 0 ? Q_B : chunk == 1 ? K_B : V_B));
        #pragma unroll
        for (int nt = 0; nt < 4; nt++) {
            const uint4* fb = g_BqkvF + (size_t)(((chunk * 4 + ng) * 4 + nt) * 256) + lane;
            float c[4] = {0.f, 0.f, 0.f, 0.f};
            #pragma unroll
            for (int kt2 = 0; kt2 < 4; kt2++) {
                uint4 bhv = __ldg(fb + kt2 * 64);
                uint4 blv = __ldg(fb + kt2 * 64 + 32);
                mma16816(c, a_hi[2 * kt2],     bhv.x, bhv.y);
                mma16816(c, a_hi[2 * kt2],     blv.x, blv.y);
                mma16816(c, a_lo[2 * kt2],     bhv.x, bhv.y);
                mma16816(c, a_hi[2 * kt2 + 1], bhv.z, bhv.w);
                mma16816(c, a_hi[2 * kt2 + 1], blv.z, blv.w);
                mma16816(c, a_lo[2 * kt2 + 1], bhv.z, bhv.w);
            }
            const int n0 = ng * 32 + nt * 8;
            int coll = n0 + 2 * (lane & 3);
            float2 bias = __ldg(reinterpret_cast<const float2*>(qkv_b + chunk * 128 + coll));
            if (r1 < NTOK)
                *reinterpret_cast<float2*>(qkvdst + r1 * 132 + coll) =
                    make_float2(c[0] + bias.x, c[1] + bias.y);
            if (r2 < NTOK)
                *reinterpret_cast<float2*>(qkvdst + r2 * 132 + coll) =
                    make_float2(c[2] + bias.x, c[3] + bias.y);
        }
    }
    __syncthreads();

    // ---- phase 2: attention (fp32 FFMA2) ----
    float4* q4 = reinterpret_cast<float4*>(smb + Q_B);
    float4* k4 = reinterpret_cast<float4*>(smb + K_B);
    float4* v4 = reinterpret_cast<float4*>(smb + V_B);
    float*  ps = reinterpret_cast<float*>(smb + P_B);
    float4* p4 = reinterpret_cast<float4*>(smb + P_B);

    // stage 3: logits + softmax -> P
    {
        const float scale = 0.17677669529663687f;   // 1/sqrt(32)
        const int j1 = lane;
        const int j2 = lane + 32;
        const int j2c = (j2 < NTOK) ? j2 : (NTOK - 1);
        const bool vld2 = (j2 < NTOK);

        for (int grp = warp; grp < 28; grp += 16) {
            const int h  = grp / 7;
            const int i0 = (grp % 7) * 7;
            const int hb = h * 8;

            u64 acc[7][2];
            #pragma unroll
            for (int ii = 0; ii < 7; ii++) { acc[ii][0] = 0ull; acc[ii][1] = 0ull; }

            #pragma unroll
            for (int d4 = 0; d4 < 8; d4++) {
                float4 k1v = k4[j1  * 33 + hb + d4];
                float4 k2v = k4[j2c * 33 + hb + d4];
                const u64* k1p = reinterpret_cast<const u64*>(&k1v);
                const u64* k2p = reinterpret_cast<const u64*>(&k2v);
                #pragma unroll
                for (int ii = 0; ii < 7; ii++) {
                    float4 qv = q4[(i0 + ii) * 33 + hb + d4];
                    const u64* qp = reinterpret_cast<const u64*>(&qv);
                    ffma2(acc[ii][0], qp[0], k1p[0]);
                    ffma2(acc[ii][0], qp[1], k1p[1]);
                    ffma2(acc[ii][1], qp[0], k2p[0]);
                    ffma2(acc[ii][1], qp[1], k2p[1]);
                }
            }
            #pragma unroll
            for (int ii = 0; ii < 7; ii++) {
                int i = i0 + ii;
                float2 a0 = unpack2(acc[ii][0]);
                float2 a1 = unpack2(acc[ii][1]);
                float s1 = a0.x + a0.y;
                float s2 = a1.x + a1.y;
                const float* comb = g_comb + ((size_t)((wi * NHEADS + h) * NTOK + i)) * NTOK;
                s1 = fmaf(s1, scale, comb[j1]);
                float s2f = fmaf(s2, scale, comb[j2c]);
                s2 = vld2 ? s2f : -INFINITY;

                float m = fmaxf(s1, s2);
                #pragma unroll
                for (int off = 16; off; off >>= 1) m = fmaxf(m, __shfl_xor_sync(0xffffffffu, m, off));
                float e1 = __expf(s1 - m);
                float e2 = vld2 ? __expf(s2 - m) : 0.f;
                float sum = e1 + e2;
                #pragma unroll
                for (int off = 16; off; off >>= 1) sum += __shfl_xor_sync(0xffffffffu, sum, off);
                float inv = 1.0f / sum;

                float* prow = ps + (h * NTOK + i) * PSTR;
                prow[j1] = e1 * inv;
                if (vld2) prow[j2] = e2 * inv;
            }
        }
    }
    __syncthreads();

    // stage 5: O = P @ V -> Q region (overwrite)
    {
        const int h = lane >> 3;
        int i0 = 4 * warp; if (i0 > 45) i0 = 45;

        u64 acc[4][2];
        #pragma unroll
        for (int ii = 0; ii < 4; ii++) { acc[ii][0] = 0ull; acc[ii][1] = 0ull; }

        #pragma unroll 4
        for (int j4 = 0; j4 < 13; j4++) {
            float4 pv[4];
            #pragma unroll
            for (int ii = 0; ii < 4; ii++)
                pv[ii] = p4[(h * NTOK + i0 + ii) * 13 + j4];
            #pragma unroll
            for (int jj = 0; jj < 4; jj++) {
                int j = 4 * j4 + jj;
                float4 vv = v4[j * 33 + lane];
                const u64* vp = reinterpret_cast<const u64*>(&vv);
                u64 d0 = dup2((&pv[0].x)[jj]);
                u64 d1 = dup2((&pv[1].x)[jj]);
                u64 d2 = dup2((&pv[2].x)[jj]);
                u64 d3 = dup2((&pv[3].x)[jj]);
                ffma2(acc[0][0], d0, vp[0]); ffma2(acc[0][1], d0, vp[1]);
                ffma2(acc[1][0], d1, vp[0]); ffma2(acc[1][1], d1, vp[1]);
                ffma2(acc[2][0], d2, vp[0]); ffma2(acc[2][1], d2, vp[1]);
                ffma2(acc[3][0], d3, vp[0]); ffma2(acc[3][1], d3, vp[1]);
            }
        }
        #pragma unroll
        for (int ii = 0; ii < 4; ii++) {
            float2 p0 = unpack2(acc[ii][0]);
            float2 p1 = unpack2(acc[ii][1]);
            q4[(i0 + ii) * 33 + lane] = make_float4(p0.x, p0.y, p1.x, p1.y);
        }
    }
    __syncthreads();

    // ---- phase 3: proj via mma, fragment-direct B ----
    {
        // O (Q region) -> A' images (pad rows still zero)
        const float* op = reinterpret_cast<const float*>(smb + Q_B);
        for (int e = tid; e < NTOK * 64; e += NTHREADS) {
            int row = e >> 6, kp = e & 63;
            float x0 = op[row * 132 + 2 * kp];
            float x1 = op[row * 132 + 2 * kp + 1];
            uint32_t hp, lp; split2(x0, x1, hp, lp);
            uint32_t o = (uint32_t)row * AROW_B + kp * 4;
            *reinterpret_cast<uint32_t*>(smb + A_HI_B + o) = hp;
            *reinterpret_cast<uint32_t*>(smb + A_LO_B + o) = lp;
        }
        __syncthreads();

        uint32_t ra = smem_base + (mt * 16 + (lane & 15)) * AROW_B + (lane >> 4) * 16;
        uint32_t o_hi[8][4], o_lo[8][4];
        #pragma unroll
        for (int k = 0; k < 8; k++) {
            ldmx4(o_hi[k], ra + A_HI_B + k * 32);
            ldmx4(o_lo[k], ra + A_LO_B + k * 32);
        }

        float* outp = out_g + (size_t)blk * (NTOK * CDIM);
        #pragma unroll
        for (int nt = 0; nt < 4; nt++) {
            const uint4* fb = g_BprojF + (size_t)((ng * 4 + nt) * 256) + lane;
            float c[4] = {0.f, 0.f, 0.f, 0.f};
            #pragma unroll
            for (int kt2 = 0; kt2 < 4; kt2++) {
                uint4 bhv = __ldg(fb + kt2 * 64);
                uint4 blv = __ldg(fb + kt2 * 64 + 32);
                mma16816(c, o_hi[2 * kt2],     bhv.x, bhv.y);
                mma16816(c, o_hi[2 * kt2],     blv.x, blv.y);
                mma16816(c, o_lo[2 * kt2],     bhv.x, bhv.y);
                mma16816(c, o_hi[2 * kt2 + 1], bhv.z, bhv.w);
                mma16816(c, o_hi[2 * kt2 + 1], blv.z, blv.w);
                mma16816(c, o_lo[2 * kt2 + 1], bhv.z, bhv.w);
            }
            const int n0 = ng * 32 + nt * 8;
            int coll = n0 + 2 * (lane & 3);
            float2 bias = __ldg(reinterpret_cast<const float2*>(proj_b + coll));
            if (r1 < NTOK)
                *reinterpret_cast<float2*>(outp + r1 * CDIM + coll) =
                    make_float2(c[0] + bias.x, c[1] + bias.y);
            if (r2 < NTOK)
                *reinterpret_cast<float2*>(outp + r2 * CDIM + coll) =
                    make_float2(c[2] + bias.x, c[3] + bias.y);
        }
    }
}

extern "C" void kernel_launch(void* const* d_in, const int* in_sizes, int n_in,
                              void* d_out, int out_size) {
    const float* x      = (const float*)d_in[0];
    const float* mask   = (const float*)d_in[1];
    const float* qkv_w  = (const float*)d_in[2];
    const float* qkv_b  = (const float*)d_in[3];
    const float* proj_w = (const float*)d_in[4];
    const float* proj_b = (const float*)d_in[5];
    const float* rel    = (const float*)d_in[6];
    float* out = (float*)d_out;

    (void)in_sizes; (void)n_in; (void)out_size;

    cudaFuncSetAttribute(swin_mma_kernel,
                         cudaFuncAttributeMaxDynamicSharedMemorySize, SMEM_TOTAL_B);

    int ncomb = NWIN * NHEADS * NTOK * NTOK;
    swin_comb_kernel<<<(ncomb + 255) / 256, 256>>>(rel, mask);
    swin_split_kernel<<<(16384 + 255) / 256, 256>>>(qkv_w, proj_w);
    swin_mma_kernel<<<NBLK, NTHREADS, SMEM_TOTAL_B>>>(x, qkv_b, proj_b, out);
}

// round 9
// speedup vs baseline: 1.5065x; 1.0444x over previous
#include <cuda_runtime.h>
#include <cuda_bf16.h>
#include <math.h>
#include <stdint.h>

#define NHEADS   4
#define WIN      7
#define NTOK     49
#define CDIM     128
#define NWIN     64
#define NBLK     2048
#define NTHREADS 512
#define PSTR     52

typedef unsigned long long u64;

// ---------------- packed fp32 helpers ----------------
__device__ __forceinline__ void ffma2(u64 &d, u64 a, u64 b) {
    asm("fma.rn.f32x2 %0, %1, %2, %3;" : "=l"(d) : "l"(a), "l"(b), "l"(d));
}
__device__ __forceinline__ u64 dup2(float x) {
    u64 r; asm("mov.b64 %0, {%1, %1};" : "=l"(r) : "f"(x)); return r;
}
__device__ __forceinline__ float2 unpack2(u64 v) {
    float2 r; asm("mov.b64 {%0, %1}, %2;" : "=f"(r.x), "=f"(r.y) : "l"(v)); return r;
}

// ---------------- mma.sync helpers ----------------
__device__ __forceinline__ uint32_t smem_u32(const void* p) {
    uint32_t a;
    asm("{ .reg .u64 t; cvta.to.shared.u64 t, %1; cvt.u32.u64 %0, t; }" : "=r"(a) : "l"(p));
    return a;
}
__device__ __forceinline__ void ldmx4(uint32_t* d, uint32_t addr) {
    asm volatile("ldmatrix.sync.aligned.m8n8.x4.shared.b16 {%0,%1,%2,%3}, [%4];"
        : "=r"(d[0]), "=r"(d[1]), "=r"(d[2]), "=r"(d[3]) : "r"(addr));
}
__device__ __forceinline__ void mma16816(float* c, const uint32_t* a, uint32_t b0, uint32_t b1) {
    asm volatile("mma.sync.aligned.m16n8k16.row.col.f32.bf16.bf16.f32 "
        "{%0,%1,%2,%3}, {%4,%5,%6,%7}, {%8,%9}, {%0,%1,%2,%3};"
        : "+f"(c[0]), "+f"(c[1]), "+f"(c[2]), "+f"(c[3])
        : "r"(a[0]), "r"(a[1]), "r"(a[2]), "r"(a[3]), "r"(b0), "r"(b1));
}

// ---------------- smem layout (bytes) ----------------
#define AROW_B    272          // 136 bf16 per row, ldmatrix conflict-free
#define A_HI_B    0
#define A_LO_B    17408
#define Q_B       34816        // 49 rows x 132 floats
#define K_B       60688
#define V_B       86560        // 52 rows x 132 floats (49..51 zero)
#define P_B       114016       // [4][49][52] floats (cols 49..51 zero)
#define SMEM_TOTAL_B 154784

// ---------------- device globals ----------------
__device__ float g_comb[NWIN * NHEADS * NTOK * NTOK];
// fragment-ordered weight images: idx = ((((chunk*4+ng)*4+nt)*4+kt2)*2+img)*32+lane
__device__ uint4 g_BqkvF[12288];
__device__ uint4 g_BprojF[4096];

__device__ __forceinline__ uint32_t pack_split(float w0, float w1, int img) {
    __nv_bfloat16 h0 = __float2bfloat16(w0);
    __nv_bfloat16 h1 = __float2bfloat16(w1);
    if (img == 0)
        return ((uint32_t)__bfloat16_as_ushort(h1) << 16) | __bfloat16_as_ushort(h0);
    __nv_bfloat16 l0 = __float2bfloat16(w0 - __bfloat162float(h0));
    __nv_bfloat16 l1 = __float2bfloat16(w1 - __bfloat162float(h1));
    return ((uint32_t)__bfloat16_as_ushort(l1) << 16) | __bfloat16_as_ushort(l0);
}

// Fused prologue: blocks [0,2401) build comb; blocks [2401,2465) build weight frags.
#define COMB_BLKS 2401
__global__ void swin_prol_kernel(const float* __restrict__ rel_table,
                                 const float* __restrict__ mask,
                                 const float* __restrict__ qkv_w,
                                 const float* __restrict__ proj_w) {
    if (blockIdx.x < COMB_BLKS) {
        int e = blockIdx.x * blockDim.x + threadIdx.x;
        if (e >= NWIN * NHEADS * NTOK * NTOK) return;
        int j = e % NTOK;
        int t = e / NTOK;
        int i = t % NTOK;  t /= NTOK;
        int h = t % NHEADS;
        int w = t / NHEADS;
        int yi = i / WIN, xi = i % WIN, yj = j / WIN, xj = j % WIN;
        int r = (yi - yj + WIN - 1) * (2 * WIN - 1) + (xi - xj + WIN - 1);
        g_comb[e] = rel_table[r * NHEADS + h] + mask[(w * NTOK + i) * NTOK + j];
    } else {
        int e = (blockIdx.x - COMB_BLKS) * blockDim.x + threadIdx.x;
        if (e >= 16384) return;
        bool isproj = (e >= 12288);
        int idx = isproj ? (e - 12288) : e;
        int lane = idx & 31;
        int img  = (idx >> 5) & 1;
        int kt2  = (idx >> 6) & 3;
        int nt   = (idx >> 8) & 3;
        int ng   = (idx >> 10) & 3;
        int chunk = isproj ? 0 : (idx >> 12);
        int n = ng * 32 + nt * 8 + (lane >> 2);
        uint32_t r[4];
        #pragma unroll
        for (int m = 0; m < 4; m++) {
            int k = kt2 * 32 + m * 8 + 2 * (lane & 3);
            float w0, w1;
            if (isproj) { w0 = proj_w[k * 128 + n];              w1 = proj_w[(k + 1) * 128 + n]; }
            else        { w0 = qkv_w[k * 384 + chunk * 128 + n]; w1 = qkv_w[(k + 1) * 384 + chunk * 128 + n]; }
            r[m] = pack_split(w0, w1, img);
        }
        uint4 v = make_uint4(r[0], r[1], r[2], r[3]);
        if (isproj) g_BprojF[idx] = v; else g_BqkvF[idx] = v;
    }
}

__device__ __forceinline__ void split2(float x0, float x1, uint32_t &hp, uint32_t &lp) {
    __nv_bfloat16 h0 = __float2bfloat16(x0);
    __nv_bfloat16 h1 = __float2bfloat16(x1);
    __nv_bfloat16 l0 = __float2bfloat16(x0 - __bfloat162float(h0));
    __nv_bfloat16 l1 = __float2bfloat16(x1 - __bfloat162float(h1));
    hp = ((uint32_t)__bfloat16_as_ushort(h1) << 16) | __bfloat16_as_ushort(h0);
    lp = ((uint32_t)__bfloat16_as_ushort(l1) << 16) | __bfloat16_as_ushort(l0);
}

__global__ __launch_bounds__(NTHREADS, 1)
void swin_mma_kernel(const float* __restrict__ x_g,
                     const float* __restrict__ qkv_b,
                     const float* __restrict__ proj_b,
                     float* __restrict__ out_g) {
    const int blk  = blockIdx.x;
    const int wi   = blk & (NWIN - 1);
    const int tid  = threadIdx.x;
    const int lane = tid & 31;
    const int warp = tid >> 5;

    extern __shared__ float smem[];
    char* smb = reinterpret_cast<char*>(smem);
    const uint32_t smem_base = smem_u32(smem);

    // ---- phase 1a: x -> A hi/lo bf16 images; zero pads ----
    {
        const float2* xin = reinterpret_cast<const float2*>(x_g + (size_t)blk * (NTOK * CDIM));
        for (int e = tid; e < NTOK * 64; e += NTHREADS) {
            int row = e >> 6, kp = e & 63;
            float2 v = xin[e];
            uint32_t hp, lp; split2(v.x, v.y, hp, lp);
            uint32_t o = (uint32_t)row * AROW_B + kp * 4;
            *reinterpret_cast<uint32_t*>(smb + A_HI_B + o) = hp;
            *reinterpret_cast<uint32_t*>(smb + A_LO_B + o) = lp;
        }
        for (int o = tid; o < 510; o += NTHREADS) {
            int img = o / 255, rem = o % 255;
            int rr = rem / 17, c = rem % 17;
            *reinterpret_cast<float4*>(smb + img * 17408 + (49 + rr) * AROW_B + c * 16) =
                make_float4(0.f, 0.f, 0.f, 0.f);
        }
        for (int o = tid; o < 99; o += NTHREADS) {
            *reinterpret_cast<float4*>(smb + V_B + (49 + o / 33) * 528 + (o % 33) * 16) =
                make_float4(0.f, 0.f, 0.f, 0.f);
        }
        float* ps = reinterpret_cast<float*>(smb + P_B);
        for (int o = tid; o < NHEADS * NTOK * 3; o += NTHREADS)
            ps[(o / 3) * PSTR + 49 + (o % 3)] = 0.f;
    }
    __syncthreads();

    const int mt = warp & 3;              // M tile (16 rows)
    const int ng = warp >> 2;             // N group (32 cols)

    // ---- phase 1b: load A fragments ----
    uint32_t a_hi[8][4], a_lo[8][4];
    {
        uint32_t ra = smem_base + (mt * 16 + (lane & 15)) * AROW_B + (lane >> 4) * 16;
        #pragma unroll
        for (int k = 0; k < 8; k++) {
            ldmx4(a_hi[k], ra + A_HI_B + k * 32);
            ldmx4(a_lo[k], ra + A_LO_B + k * 32);
        }
    }

    // ---- phase 1c: QKV GEMM, fragment-direct B ----
    const int r1 = mt * 16 + (lane >> 2);
    const int r2 = r1 + 8;
    #pragma unroll
    for (int chunk = 0; chunk < 3; chunk++) {
        float* qkvdst = reinterpret_cast<float*>(smb + (chunk == 0 ? Q_B : chunk == 1 ? K_B : V_B));
        #pragma unroll
        for (int nt = 0; nt < 4; nt++) {
            const uint4* fb = g_BqkvF + (size_t)(((chunk * 4 + ng) * 4 + nt) * 256) + lane;
            float c[4] = {0.f, 0.f, 0.f, 0.f};
            #pragma unroll
            for (int kt2 = 0; kt2 < 4; kt2++) {
                uint4 bhv = __ldg(fb + kt2 * 64);
                uint4 blv = __ldg(fb + kt2 * 64 + 32);
                mma16816(c, a_hi[2 * kt2],     bhv.x, bhv.y);
                mma16816(c, a_hi[2 * kt2],     blv.x, blv.y);
                mma16816(c, a_lo[2 * kt2],     bhv.x, bhv.y);
                mma16816(c, a_hi[2 * kt2 + 1], bhv.z, bhv.w);
                mma16816(c, a_hi[2 * kt2 + 1], blv.z, blv.w);
                mma16816(c, a_lo[2 * kt2 + 1], bhv.z, bhv.w);
            }
            const int n0 = ng * 32 + nt * 8;
            int coll = n0 + 2 * (lane & 3);
            float2 bias = __ldg(reinterpret_cast<const float2*>(qkv_b + chunk * 128 + coll));
            if (r1 < NTOK)
                *reinterpret_cast<float2*>(qkvdst + r1 * 132 + coll) =
                    make_float2(c[0] + bias.x, c[1] + bias.y);
            if (r2 < NTOK)
                *reinterpret_cast<float2*>(qkvdst + r2 * 132 + coll) =
                    make_float2(c[2] + bias.x, c[3] + bias.y);
        }
    }
    __syncthreads();

    // ---- phase 2: attention (fp32 FFMA2) ----
    float4* q4 = reinterpret_cast<float4*>(smb + Q_B);
    float4* k4 = reinterpret_cast<float4*>(smb + K_B);
    float4* v4 = reinterpret_cast<float4*>(smb + V_B);
    float*  ps = reinterpret_cast<float*>(smb + P_B);
    float4* p4 = reinterpret_cast<float4*>(smb + P_B);

    // stage 3: logits + softmax (no max pass: logits provably tiny) -> P
    // 32 exact groups: 4 heads x 8 i-chunks (sizes 7,6,6,6,6,6,6,6)
    {
        const float scale = 0.17677669529663687f;   // 1/sqrt(32)
        const int j1 = lane;
        const int j2 = lane + 32;
        const int j2c = (j2 < NTOK) ? j2 : (NTOK - 1);
        const bool vld2 = (j2 < NTOK);

        #pragma unroll
        for (int g = 0; g < 2; g++) {
            const int grp = warp * 2 + g;        // 0..31
            const int h   = grp >> 3;
            const int ch  = grp & 7;
            const int i0  = ch ? (6 * ch + 1) : 0;
            const int cnt = ch ? 6 : 7;
            const int hb  = h * 8;

            int ir[7];
            #pragma unroll
            for (int ii = 0; ii < 7; ii++) ir[ii] = (ii < cnt) ? (i0 + ii) : i0;

            u64 acc[7][2];
            #pragma unroll
            for (int ii = 0; ii < 7; ii++) { acc[ii][0] = 0ull; acc[ii][1] = 0ull; }

            #pragma unroll
            for (int d4 = 0; d4 < 8; d4++) {
                float4 k1v = k4[j1  * 33 + hb + d4];
                float4 k2v = k4[j2c * 33 + hb + d4];
                const u64* k1p = reinterpret_cast<const u64*>(&k1v);
                const u64* k2p = reinterpret_cast<const u64*>(&k2v);
                #pragma unroll
                for (int ii = 0; ii < 7; ii++) {
                    float4 qv = q4[ir[ii] * 33 + hb + d4];
                    const u64* qp = reinterpret_cast<const u64*>(&qv);
                    ffma2(acc[ii][0], qp[0], k1p[0]);
                    ffma2(acc[ii][0], qp[1], k1p[1]);
                    ffma2(acc[ii][1], qp[0], k2p[0]);
                    ffma2(acc[ii][1], qp[1], k2p[1]);
                }
            }
            #pragma unroll
            for (int ii = 0; ii < 7; ii++) {
                float2 a0 = unpack2(acc[ii][0]);
                float2 a1 = unpack2(acc[ii][1]);
                float s1 = a0.x + a0.y;
                float s2 = a1.x + a1.y;
                const float* comb = g_comb + ((size_t)((wi * NHEADS + h) * NTOK + ir[ii])) * NTOK;
                s1 = fmaf(s1, scale, comb[j1]);
                float e1 = __expf(s1);
                float e2 = vld2 ? __expf(fmaf(s2, scale, comb[j2c])) : 0.f;
                float sum = e1 + e2;
                #pragma unroll
                for (int off = 16; off; off >>= 1) sum += __shfl_xor_sync(0xffffffffu, sum, off);
                float inv = 1.0f / sum;

                if (ii < cnt) {
                    float* prow = ps + (h * NTOK + i0 + ii) * PSTR;
                    prow[j1] = e1 * inv;
                    if (vld2) prow[j2] = e2 * inv;
                }
            }
        }
    }
    __syncthreads();

    // stage 5: O = P @ V -> Q region (overwrite; rows 49..51 spill into dead K region)
    {
        const int h = lane >> 3;
        int i0 = 4 * warp; if (i0 > 45) i0 = 45;

        u64 acc[4][2];
        #pragma unroll
        for (int ii = 0; ii < 4; ii++) { acc[ii][0] = 0ull; acc[ii][1] = 0ull; }

        #pragma unroll 4
        for (int j4 = 0; j4 < 13; j4++) {
            float4 pv[4];
            #pragma unroll
            for (int ii = 0; ii < 4; ii++)
                pv[ii] = p4[(h * NTOK + i0 + ii) * 13 + j4];
            #pragma unroll
            for (int jj = 0; jj < 4; jj++) {
                int j = 4 * j4 + jj;
                float4 vv = v4[j * 33 + lane];
                const u64* vp = reinterpret_cast<const u64*>(&vv);
                u64 d0 = dup2((&pv[0].x)[jj]);
                u64 d1 = dup2((&pv[1].x)[jj]);
                u64 d2 = dup2((&pv[2].x)[jj]);
                u64 d3 = dup2((&pv[3].x)[jj]);
                ffma2(acc[0][0], d0, vp[0]); ffma2(acc[0][1], d0, vp[1]);
                ffma2(acc[1][0], d1, vp[0]); ffma2(acc[1][1], d1, vp[1]);
                ffma2(acc[2][0], d2, vp[0]); ffma2(acc[2][1], d2, vp[1]);
                ffma2(acc[3][0], d3, vp[0]); ffma2(acc[3][1], d3, vp[1]);
            }
        }
        #pragma unroll
        for (int ii = 0; ii < 4; ii++) {
            float2 p0 = unpack2(acc[ii][0]);
            float2 p1 = unpack2(acc[ii][1]);
            q4[(i0 + ii) * 33 + lane] = make_float4(p0.x, p0.y, p1.x, p1.y);
        }
    }
    __syncthreads();

    // ---- phase 3: proj via mma, fragment-direct B ----
    {
        const float* op = reinterpret_cast<const float*>(smb + Q_B);
        for (int e = tid; e < NTOK * 64; e += NTHREADS) {
            int row = e >> 6, kp = e & 63;
            float x0 = op[row * 132 + 2 * kp];
            float x1 = op[row * 132 + 2 * kp + 1];
            uint32_t hp, lp; split2(x0, x1, hp, lp);
            uint32_t o = (uint32_t)row * AROW_B + kp * 4;
            *reinterpret_cast<uint32_t*>(smb + A_HI_B + o) = hp;
            *reinterpret_cast<uint32_t*>(smb + A_LO_B + o) = lp;
        }
        __syncthreads();

        uint32_t ra = smem_base + (mt * 16 + (lane & 15)) * AROW_B + (lane >> 4) * 16;
        uint32_t o_hi[8][4], o_lo[8][4];
        #pragma unroll
        for (int k = 0; k < 8; k++) {
            ldmx4(o_hi[k], ra + A_HI_B + k * 32);
            ldmx4(o_lo[k], ra + A_LO_B + k * 32);
        }

        float* outp = out_g + (size_t)blk * (NTOK * CDIM);
        #pragma unroll
        for (int nt = 0; nt < 4; nt++) {
            const uint4* fb = g_BprojF + (size_t)((ng * 4 + nt) * 256) + lane;
            float c[4] = {0.f, 0.f, 0.f, 0.f};
            #pragma unroll
            for (int kt2 = 0; kt2 < 4; kt2++) {
                uint4 bhv = __ldg(fb + kt2 * 64);
                uint4 blv = __ldg(fb + kt2 * 64 + 32);
                mma16816(c, o_hi[2 * kt2],     bhv.x, bhv.y);
                mma16816(c, o_hi[2 * kt2],     blv.x, blv.y);
                mma16816(c, o_lo[2 * kt2],     bhv.x, bhv.y);
                mma16816(c, o_hi[2 * kt2 + 1], bhv.z, bhv.w);
                mma16816(c, o_hi[2 * kt2 + 1], blv.z, blv.w);
                mma16816(c, o_lo[2 * kt2 + 1], bhv.z, bhv.w);
            }
            const int n0 = ng * 32 + nt * 8;
            int coll = n0 + 2 * (lane & 3);
            float2 bias = __ldg(reinterpret_cast<const float2*>(proj_b + coll));
            if (r1 < NTOK)
                *reinterpret_cast<float2*>(outp + r1 * CDIM + coll) =
                    make_float2(c[0] + bias.x, c[1] + bias.y);
            if (r2 < NTOK)
                *reinterpret_cast<float2*>(outp + r2 * CDIM + coll) =
                    make_float2(c[2] + bias.x, c[3] + bias.y);
        }
    }
}

extern "C" void kernel_launch(void* const* d_in, const int* in_sizes, int n_in,
                              void* d_out, int out_size) {
    const float* x      = (const float*)d_in[0];
    const float* mask   = (const float*)d_in[1];
    const float* qkv_w  = (const float*)d_in[2];
    const float* qkv_b  = (const float*)d_in[3];
    const float* proj_w = (const float*)d_in[4];
    const float* proj_b = (const float*)d_in[5];
    const float* rel    = (const float*)d_in[6];
    float* out = (float*)d_out;

    (void)in_sizes; (void)n_in; (void)out_size;

    cudaFuncSetAttribute(swin_mma_kernel,
                         cudaFuncAttributeMaxDynamicSharedMemorySize, SMEM_TOTAL_B);

    swin_prol_kernel<<<COMB_BLKS + 64, 256>>>(rel, mask, qkv_w, proj_w);
    swin_mma_kernel<<<NBLK, NTHREADS, SMEM_TOTAL_B>>>(x, qkv_b, proj_b, out);
}

// round 10
// speedup vs baseline: 1.6606x; 1.1023x over previous
#include <cuda_runtime.h>
#include <cuda_bf16.h>
#include <math.h>
#include <stdint.h>

#define NHEADS   4
#define WIN      7
#define NTOK     49
#define CDIM     128
#define NWIN     64
#define NBLK     2048
#define NTHREADS 256

typedef unsigned long long u64;

// ---------------- packed fp32 helpers ----------------
__device__ __forceinline__ void ffma2(u64 &d, u64 a, u64 b) {
    asm("fma.rn.f32x2 %0, %1, %2, %3;" : "=l"(d) : "l"(a), "l"(b), "l"(d));
}
__device__ __forceinline__ u64 dup2(float x) {
    u64 r; asm("mov.b64 %0, {%1, %1};" : "=l"(r) : "f"(x)); return r;
}
__device__ __forceinline__ float2 unpack2(u64 v) {
    float2 r; asm("mov.b64 {%0, %1}, %2;" : "=f"(r.x), "=f"(r.y) : "l"(v)); return r;
}

// ---------------- mma.sync helpers ----------------
__device__ __forceinline__ uint32_t smem_u32(const void* p) {
    uint32_t a;
    asm("{ .reg .u64 t; cvta.to.shared.u64 t, %1; cvt.u32.u64 %0, t; }" : "=r"(a) : "l"(p));
    return a;
}
__device__ __forceinline__ void ldmx4(uint32_t* d, uint32_t addr) {
    asm volatile("ldmatrix.sync.aligned.m8n8.x4.shared.b16 {%0,%1,%2,%3}, [%4];"
        : "=r"(d[0]), "=r"(d[1]), "=r"(d[2]), "=r"(d[3]) : "r"(addr));
}
__device__ __forceinline__ void mma16816(float* c, const uint32_t* a, uint32_t b0, uint32_t b1) {
    asm volatile("mma.sync.aligned.m16n8k16.row.col.f32.bf16.bf16.f32 "
        "{%0,%1,%2,%3}, {%4,%5,%6,%7}, {%8,%9}, {%0,%1,%2,%3};"
        : "+f"(c[0]), "+f"(c[1]), "+f"(c[2]), "+f"(c[3])
        : "r"(a[0]), "r"(a[1]), "r"(a[2]), "r"(a[3]), "r"(b0), "r"(b1));
}

// ---------------- smem layout (bytes), 2 CTAs/SM budget ----------------
#define AROW_B    272          // 136 bf16 per row (ldmatrix conflict-free)
// region 0: A images (phase1) / P [4][49][49] fp32 (stage3-5) / A' images (phase3)
#define A_HI_B    0            // 49 rows x 272B
#define A_LO_B    13328
#define P_B       0            // 196 rows x 49 floats = 38416
#define Q_B       38416        // 49 rows x 128 floats (stride 32 f4) = 25088
#define K_B       63504        // 49 rows x 132 floats (stride 33 f4) = 25872
#define V_B       89376        // 49 rows x 128 floats (stride 32 f4) = 25088
#define SMEM_TOTAL_B 114464    // <= 114688 (14 x 8KB pages) -> 2 CTAs/SM

// ---------------- device globals ----------------
__device__ float g_comb[NWIN * NHEADS * NTOK * NTOK];
// fragment-ordered weight images: idx = ((((chunk*4+ng)*4+nt)*4+kt2)*2+img)*32+lane
__device__ uint4 g_BqkvF[12288];
__device__ uint4 g_BprojF[4096];

__device__ __forceinline__ uint32_t pack_split(float w0, float w1, int img) {
    __nv_bfloat16 h0 = __float2bfloat16(w0);
    __nv_bfloat16 h1 = __float2bfloat16(w1);
    if (img == 0)
        return ((uint32_t)__bfloat16_as_ushort(h1) << 16) | __bfloat16_as_ushort(h0);
    __nv_bfloat16 l0 = __float2bfloat16(w0 - __bfloat162float(h0));
    __nv_bfloat16 l1 = __float2bfloat16(w1 - __bfloat162float(h1));
    return ((uint32_t)__bfloat16_as_ushort(l1) << 16) | __bfloat16_as_ushort(l0);
}

// Fused prologue: blocks [0,2401) build comb; blocks [2401,2465) build weight frags.
#define COMB_BLKS 2401
__global__ void swin_prol_kernel(const float* __restrict__ rel_table,
                                 const float* __restrict__ mask,
                                 const float* __restrict__ qkv_w,
                                 const float* __restrict__ proj_w) {
    if (blockIdx.x < COMB_BLKS) {
        int e = blockIdx.x * blockDim.x + threadIdx.x;
        if (e >= NWIN * NHEADS * NTOK * NTOK) return;
        int j = e % NTOK;
        int t = e / NTOK;
        int i = t % NTOK;  t /= NTOK;
        int h = t % NHEADS;
        int w = t / NHEADS;
        int yi = i / WIN, xi = i % WIN, yj = j / WIN, xj = j % WIN;
        int r = (yi - yj + WIN - 1) * (2 * WIN - 1) + (xi - xj + WIN - 1);
        g_comb[e] = rel_table[r * NHEADS + h] + mask[(w * NTOK + i) * NTOK + j];
    } else {
        int e = (blockIdx.x - COMB_BLKS) * blockDim.x + threadIdx.x;
        if (e >= 16384) return;
        bool isproj = (e >= 12288);
        int idx = isproj ? (e - 12288) : e;
        int lane = idx & 31;
        int img  = (idx >> 5) & 1;
        int kt2  = (idx >> 6) & 3;
        int nt   = (idx >> 8) & 3;
        int ng   = (idx >> 10) & 3;
        int chunk = isproj ? 0 : (idx >> 12);
        int n = ng * 32 + nt * 8 + (lane >> 2);
        uint32_t r[4];
        #pragma unroll
        for (int m = 0; m < 4; m++) {
            int k = kt2 * 32 + m * 8 + 2 * (lane & 3);
            float w0, w1;
            if (isproj) { w0 = proj_w[k * 128 + n];              w1 = proj_w[(k + 1) * 128 + n]; }
            else        { w0 = qkv_w[k * 384 + chunk * 128 + n]; w1 = qkv_w[(k + 1) * 384 + chunk * 128 + n]; }
            r[m] = pack_split(w0, w1, img);
        }
        uint4 v = make_uint4(r[0], r[1], r[2], r[3]);
        if (isproj) g_BprojF[idx] = v; else g_BqkvF[idx] = v;
    }
}

__device__ __forceinline__ void split2(float x0, float x1, uint32_t &hp, uint32_t &lp) {
    __nv_bfloat16 h0 = __float2bfloat16(x0);
    __nv_bfloat16 h1 = __float2bfloat16(x1);
    __nv_bfloat16 l0 = __float2bfloat16(x0 - __bfloat162float(h0));
    __nv_bfloat16 l1 = __float2bfloat16(x1 - __bfloat162float(h1));
    hp = ((uint32_t)__bfloat16_as_ushort(h1) << 16) | __bfloat16_as_ushort(h0);
    lp = ((uint32_t)__bfloat16_as_ushort(l1) << 16) | __bfloat16_as_ushort(l0);
}

__global__ __launch_bounds__(NTHREADS, 2)
void swin_mma_kernel(const float* __restrict__ x_g,
                     const float* __restrict__ qkv_b,
                     const float* __restrict__ proj_b,
                     float* __restrict__ out_g) {
    const int blk  = blockIdx.x;
    const int wi   = blk & (NWIN - 1);
    const int tid  = threadIdx.x;
    const int lane = tid & 31;
    const int warp = tid >> 5;            // 0..7

    extern __shared__ float smem[];
    char* smb = reinterpret_cast<char*>(smem);
    const uint32_t smem_base = smem_u32(smem);

    // ---- phase 1a: x -> A hi/lo bf16 images (49 rows, no pads) ----
    {
        const float2* xin = reinterpret_cast<const float2*>(x_g + (size_t)blk * (NTOK * CDIM));
        for (int e = tid; e < NTOK * 64; e += NTHREADS) {
            int row = e >> 6, kp = e & 63;
            float2 v = xin[e];
            uint32_t hp, lp; split2(v.x, v.y, hp, lp);
            uint32_t o = (uint32_t)row * AROW_B + kp * 4;
            *reinterpret_cast<uint32_t*>(smb + A_HI_B + o) = hp;
            *reinterpret_cast<uint32_t*>(smb + A_LO_B + o) = lp;
        }
    }
    __syncthreads();

    const int mt  = warp & 3;                       // M tile
    const int ng2 = warp >> 2;                      // N half (64 cols)
    const int mtb = (mt < 3) ? mt * 16 : 33;        // overlapping last tile: rows 33..48

    // ---- phase 1b: load A fragments ----
    uint32_t a_hi[8][4], a_lo[8][4];
    {
        uint32_t ra = smem_base + (mtb + (lane & 15)) * AROW_B + (lane >> 4) * 16;
        #pragma unroll
        for (int k = 0; k < 8; k++) {
            ldmx4(a_hi[k], ra + A_HI_B + k * 32);
            ldmx4(a_lo[k], ra + A_LO_B + k * 32);
        }
    }

    // ---- phase 1c: QKV GEMM, fragment-direct B; rows all < 49 (no guards) ----
    const int r1 = mtb + (lane >> 2);
    const int r2 = r1 + 8;
    #pragma unroll
    for (int chunk = 0; chunk < 3; chunk++) {
        float* dstf = reinterpret_cast<float*>(smb + (chunk == 0 ? Q_B : chunk == 1 ? K_B : V_B));
        const int rs = (chunk == 1) ? 132 : 128;
        #pragma unroll
        for (int nt8 = 0; nt8 < 8; nt8++) {
            const int ng4 = ng2 * 2 + (nt8 >> 2);
            const int nt4 = nt8 & 3;
            const uint4* fb = g_BqkvF + (size_t)(((chunk * 4 + ng4) * 4 + nt4) * 256) + lane;
            float c[4] = {0.f, 0.f, 0.f, 0.f};
            #pragma unroll
            for (int kt2 = 0; kt2 < 4; kt2++) {
                uint4 bhv = __ldg(fb + kt2 * 64);
                uint4 blv = __ldg(fb + kt2 * 64 + 32);
                mma16816(c, a_hi[2 * kt2],     bhv.x, bhv.y);
                mma16816(c, a_hi[2 * kt2],     blv.x, blv.y);
                mma16816(c, a_lo[2 * kt2],     bhv.x, bhv.y);
                mma16816(c, a_hi[2 * kt2 + 1], bhv.z, bhv.w);
                mma16816(c, a_hi[2 * kt2 + 1], blv.z, blv.w);
                mma16816(c, a_lo[2 * kt2 + 1], bhv.z, bhv.w);
            }
            const int n0 = ng2 * 64 + nt8 * 8;
            int coll = n0 + 2 * (lane & 3);
            float2 bias = __ldg(reinterpret_cast<const float2*>(qkv_b + chunk * 128 + coll));
            *reinterpret_cast<float2*>(dstf + r1 * rs + coll) = make_float2(c[0] + bias.x, c[1] + bias.y);
            *reinterpret_cast<float2*>(dstf + r2 * rs + coll) = make_float2(c[2] + bias.x, c[3] + bias.y);
        }
    }
    __syncthreads();

    // ---- stage 3: logits + softmax (no max pass; logits tiny) -> P [4][49][49] ----
    float4* q4 = reinterpret_cast<float4*>(smb + Q_B);   // stride 32 f4
    float4* k4 = reinterpret_cast<float4*>(smb + K_B);   // stride 33 f4
    float4* v4 = reinterpret_cast<float4*>(smb + V_B);   // stride 32 f4
    float*  ps = reinterpret_cast<float*>(smb + P_B);
    {
        const float scale = 0.17677669529663687f;   // 1/sqrt(32)
        const int j1 = lane;
        const int j2 = lane + 32;
        const int j2c = (j2 < NTOK) ? j2 : (NTOK - 1);
        const bool vld2 = (j2 < NTOK);

        #pragma unroll
        for (int g = 0; g < 4; g++) {
            const int grp = warp * 4 + g;        // 0..31
            const int h   = grp >> 3;
            const int ch  = grp & 7;
            const int i0  = ch ? (6 * ch + 1) : 0;
            const int cnt = ch ? 6 : 7;
            const int hb  = h * 8;

            int ir[7];
            #pragma unroll
            for (int ii = 0; ii < 7; ii++) ir[ii] = (ii < cnt) ? (i0 + ii) : i0;

            u64 acc[7][2];
            #pragma unroll
            for (int ii = 0; ii < 7; ii++) { acc[ii][0] = 0ull; acc[ii][1] = 0ull; }

            #pragma unroll
            for (int d4 = 0; d4 < 8; d4++) {
                float4 k1v = k4[j1  * 33 + hb + d4];
                float4 k2v = k4[j2c * 33 + hb + d4];
                const u64* k1p = reinterpret_cast<const u64*>(&k1v);
                const u64* k2p = reinterpret_cast<const u64*>(&k2v);
                #pragma unroll
                for (int ii = 0; ii < 7; ii++) {
                    float4 qv = q4[ir[ii] * 32 + hb + d4];
                    const u64* qp = reinterpret_cast<const u64*>(&qv);
                    ffma2(acc[ii][0], qp[0], k1p[0]);
                    ffma2(acc[ii][0], qp[1], k1p[1]);
                    ffma2(acc[ii][1], qp[0], k2p[0]);
                    ffma2(acc[ii][1], qp[1], k2p[1]);
                }
            }
            #pragma unroll
            for (int ii = 0; ii < 7; ii++) {
                float2 a0 = unpack2(acc[ii][0]);
                float2 a1 = unpack2(acc[ii][1]);
                float s1 = a0.x + a0.y;
                float s2 = a1.x + a1.y;
                const float* comb = g_comb + ((size_t)((wi * NHEADS + h) * NTOK + ir[ii])) * NTOK;
                s1 = fmaf(s1, scale, comb[j1]);
                float e1 = __expf(s1);
                float e2 = vld2 ? __expf(fmaf(s2, scale, comb[j2c])) : 0.f;
                float sum = e1 + e2;
                #pragma unroll
                for (int off = 16; off; off >>= 1) sum += __shfl_xor_sync(0xffffffffu, sum, off);
                float inv = 1.0f / sum;

                if (ii < cnt) {
                    float* prow = ps + (h * NTOK + i0 + ii) * NTOK;
                    prow[j1] = e1 * inv;
                    if (vld2) prow[j2] = e2 * inv;
                }
            }
        }
    }
    __syncthreads();

    // ---- stage 5: O = P @ V -> Q region (7 rows per warp; warp 7 duplicates 42..48) ----
    {
        const int h = lane >> 3;                 // head of this lane's 4 channels
        const int i0 = (warp < 7) ? 7 * warp : 42;
        const float* pbase = ps + (size_t)(h * NTOK + i0) * NTOK;

        u64 acc[7][2];
        #pragma unroll
        for (int ii = 0; ii < 7; ii++) { acc[ii][0] = 0ull; acc[ii][1] = 0ull; }

        #pragma unroll 7
        for (int j = 0; j < NTOK; j++) {
            float4 vv = v4[j * 32 + lane];
            const u64* vp = reinterpret_cast<const u64*>(&vv);
            #pragma unroll
            for (int ii = 0; ii < 7; ii++) {
                u64 d = dup2(pbase[ii * NTOK + j]);
                ffma2(acc[ii][0], d, vp[0]);
                ffma2(acc[ii][1], d, vp[1]);
            }
        }
        #pragma unroll
        for (int ii = 0; ii < 7; ii++) {
            float2 p0 = unpack2(acc[ii][0]);
            float2 p1 = unpack2(acc[ii][1]);
            q4[(i0 + ii) * 32 + lane] = make_float4(p0.x, p0.y, p1.x, p1.y);
        }
    }
    __syncthreads();

    // ---- phase 3: proj via mma; A' images over dead P region ----
    {
        const float* op = reinterpret_cast<const float*>(smb + Q_B);
        for (int e = tid; e < NTOK * 64; e += NTHREADS) {
            int row = e >> 6, kp = e & 63;
            float x0 = op[row * 128 + 2 * kp];
            float x1 = op[row * 128 + 2 * kp + 1];
            uint32_t hp, lp; split2(x0, x1, hp, lp);
            uint32_t o = (uint32_t)row * AROW_B + kp * 4;
            *reinterpret_cast<uint32_t*>(smb + A_HI_B + o) = hp;
            *reinterpret_cast<uint32_t*>(smb + A_LO_B + o) = lp;
        }
        __syncthreads();

        uint32_t ra = smem_base + (mtb + (lane & 15)) * AROW_B + (lane >> 4) * 16;
        uint32_t o_hi[8][4], o_lo[8][4];
        #pragma unroll
        for (int k = 0; k < 8; k++) {
            ldmx4(o_hi[k], ra + A_HI_B + k * 32);
            ldmx4(o_lo[k], ra + A_LO_B + k * 32);
        }

        float* outp = out_g + (size_t)blk * (NTOK * CDIM);
        #pragma unroll
        for (int nt8 = 0; nt8 < 8; nt8++) {
            const int ng4 = ng2 * 2 + (nt8 >> 2);
            const int nt4 = nt8 & 3;
            const uint4* fb = g_BprojF + (size_t)((ng4 * 4 + nt4) * 256) + lane;
            float c[4] = {0.f, 0.f, 0.f, 0.f};
            #pragma unroll
            for (int kt2 = 0; kt2 < 4; kt2++) {
                uint4 bhv = __ldg(fb + kt2 * 64);
                uint4 blv = __ldg(fb + kt2 * 64 + 32);
                mma16816(c, o_hi[2 * kt2],     bhv.x, bhv.y);
                mma16816(c, o_hi[2 * kt2],     blv.x, blv.y);
                mma16816(c, o_lo[2 * kt2],     bhv.x, bhv.y);
                mma16816(c, o_hi[2 * kt2 + 1], bhv.z, bhv.w);
                mma16816(c, o_hi[2 * kt2 + 1], blv.z, blv.w);
                mma16816(c, o_lo[2 * kt2 + 1], bhv.z, bhv.w);
            }
            const int n0 = ng2 * 64 + nt8 * 8;
            int coll = n0 + 2 * (lane & 3);
            float2 bias = __ldg(reinterpret_cast<const float2*>(proj_b + coll));
            *reinterpret_cast<float2*>(outp + r1 * CDIM + coll) = make_float2(c[0] + bias.x, c[1] + bias.y);
            *reinterpret_cast<float2*>(outp + r2 * CDIM + coll) = make_float2(c[2] + bias.x, c[3] + bias.y);
        }
    }
}

extern "C" void kernel_launch(void* const* d_in, const int* in_sizes, int n_in,
                              void* d_out, int out_size) {
    const float* x      = (const float*)d_in[0];
    const float* mask   = (const float*)d_in[1];
    const float* qkv_w  = (const float*)d_in[2];
    const float* qkv_b  = (const float*)d_in[3];
    const float* proj_w = (const float*)d_in[4];
    const float* proj_b = (const float*)d_in[5];
    const float* rel    = (const float*)d_in[6];
    float* out = (float*)d_out;

    (void)in_sizes; (void)n_in; (void)out_size;

    cudaFuncSetAttribute(swin_mma_kernel,
                         cudaFuncAttributeMaxDynamicSharedMemorySize, SMEM_TOTAL_B);

    swin_prol_kernel<<<COMB_BLKS + 64, 256>>>(rel, mask, qkv_w, proj_w);
    swin_mma_kernel<<<NBLK, NTHREADS, SMEM_TOTAL_B>>>(x, qkv_b, proj_b, out);
}

// round 11
// speedup vs baseline: 2.0230x; 1.2182x over previous
#include <cuda_runtime.h>
#include <cuda_bf16.h>
#include <math.h>
#include <stdint.h>

#define NHEADS   4
#define WIN      7
#define NTOK     49
#define CDIM     128
#define NWIN     64
#define NBLK     2048
#define NTHREADS 256

// ---------------- mma.sync helpers ----------------
__device__ __forceinline__ uint32_t smem_u32(const void* p) {
    uint32_t a;
    asm("{ .reg .u64 t; cvta.to.shared.u64 t, %1; cvt.u32.u64 %0, t; }" : "=r"(a) : "l"(p));
    return a;
}
__device__ __forceinline__ void ldmx4(uint32_t* d, uint32_t addr) {
    asm volatile("ldmatrix.sync.aligned.m8n8.x4.shared.b16 {%0,%1,%2,%3}, [%4];"
        : "=r"(d[0]), "=r"(d[1]), "=r"(d[2]), "=r"(d[3]) : "r"(addr));
}
__device__ __forceinline__ void mma16816(float* c, const uint32_t* a, uint32_t b0, uint32_t b1) {
    asm volatile("mma.sync.aligned.m16n8k16.row.col.f32.bf16.bf16.f32 "
        "{%0,%1,%2,%3}, {%4,%5,%6,%7}, {%8,%9}, {%0,%1,%2,%3};"
        : "+f"(c[0]), "+f"(c[1]), "+f"(c[2]), "+f"(c[3])
        : "r"(a[0]), "r"(a[1]), "r"(a[2]), "r"(a[3]), "r"(b0), "r"(b1));
}
__device__ __forceinline__ void split2(float x0, float x1, uint32_t &hp, uint32_t &lp) {
    __nv_bfloat16 h0 = __float2bfloat16(x0);
    __nv_bfloat16 h1 = __float2bfloat16(x1);
    __nv_bfloat16 l0 = __float2bfloat16(x0 - __bfloat162float(h0));
    __nv_bfloat16 l1 = __float2bfloat16(x1 - __bfloat162float(h1));
    hp = ((uint32_t)__bfloat16_as_ushort(h1) << 16) | __bfloat16_as_ushort(h0);
    lp = ((uint32_t)__bfloat16_as_ushort(l1) << 16) | __bfloat16_as_ushort(l0);
}

// ---------------- smem regions (bytes); all images XOR-swizzled ----------------
// A/x imgs: 49 rows x 256B each (hi/lo).  Q imgs: same.  K imgs: 56 rows x 256B.
// V^T imgs: 128 rows x 128B.  Overlays: P (4 heads x 49 x 128B, hi over RA, lo over RQ);
// A' (O) imgs over RK.
#define RA_HI   0
#define RA_LO   12544
#define RQ_HI   25088
#define RQ_LO   37632
#define RK_HI   50176
#define RK_LO   64512
#define RVT_HI  78848
#define RVT_LO  95232
#define SMEM_TOTAL_B 111616
#define P_HI(h) ((h) * 6272)
#define P_LO(h) (25088 + (h) * 6272)
#define AP_HI   50176
#define AP_LO   62720

// ---------------- device globals ----------------
__device__ float g_comb2[NWIN * NHEADS * NTOK * 64];   // padded to 64 cols
__device__ uint4 g_BqkvF[12288];
__device__ uint4 g_BprojF[4096];

__device__ __forceinline__ uint32_t pack_split(float w0, float w1, int img) {
    __nv_bfloat16 h0 = __float2bfloat16(w0);
    __nv_bfloat16 h1 = __float2bfloat16(w1);
    if (img == 0)
        return ((uint32_t)__bfloat16_as_ushort(h1) << 16) | __bfloat16_as_ushort(h0);
    __nv_bfloat16 l0 = __float2bfloat16(w0 - __bfloat162float(h0));
    __nv_bfloat16 l1 = __float2bfloat16(w1 - __bfloat162float(h1));
    return ((uint32_t)__bfloat16_as_ushort(l1) << 16) | __bfloat16_as_ushort(l0);
}

#define COMB_BLKS 2401
__global__ void swin_prol_kernel(const float* __restrict__ rel_table,
                                 const float* __restrict__ mask,
                                 const float* __restrict__ qkv_w,
                                 const float* __restrict__ proj_w) {
    if (blockIdx.x < COMB_BLKS) {
        int e = blockIdx.x * blockDim.x + threadIdx.x;
        if (e >= NWIN * NHEADS * NTOK * NTOK) return;
        int j = e % NTOK;
        int t = e / NTOK;
        int i = t % NTOK;  t /= NTOK;
        int h = t % NHEADS;
        int w = t / NHEADS;
        int yi = i / WIN, xi = i % WIN, yj = j / WIN, xj = j % WIN;
        int r = (yi - yj + WIN - 1) * (2 * WIN - 1) + (xi - xj + WIN - 1);
        g_comb2[(((w * NHEADS + h) * NTOK) + i) * 64 + j] =
            rel_table[r * NHEADS + h] + mask[(w * NTOK + i) * NTOK + j];
    } else {
        int e = (blockIdx.x - COMB_BLKS) * blockDim.x + threadIdx.x;
        if (e >= 16384) return;
        bool isproj = (e >= 12288);
        int idx = isproj ? (e - 12288) : e;
        int lane = idx & 31;
        int img  = (idx >> 5) & 1;
        int kt2  = (idx >> 6) & 3;
        int nt   = (idx >> 8) & 3;
        int ng   = (idx >> 10) & 3;
        int chunk = isproj ? 0 : (idx >> 12);
        int n = ng * 32 + nt * 8 + (lane >> 2);
        uint32_t r[4];
        #pragma unroll
        for (int m = 0; m < 4; m++) {
            int k = kt2 * 32 + m * 8 + 2 * (lane & 3);
            float w0, w1;
            if (isproj) { w0 = proj_w[k * 128 + n];              w1 = proj_w[(k + 1) * 128 + n]; }
            else        { w0 = qkv_w[k * 384 + chunk * 128 + n]; w1 = qkv_w[(k + 1) * 384 + chunk * 128 + n]; }
            r[m] = pack_split(w0, w1, img);
        }
        uint4 v = make_uint4(r[0], r[1], r[2], r[3]);
        if (isproj) g_BprojF[idx] = v; else g_BqkvF[idx] = v;
    }
}

__global__ __launch_bounds__(NTHREADS, 2)
void swin_mma_kernel(const float* __restrict__ x_g,
                     const float* __restrict__ qkv_b,
                     const float* __restrict__ proj_b,
                     float* __restrict__ out_g) {
    const int blk  = blockIdx.x;
    const int wi   = blk & (NWIN - 1);
    const int tid  = threadIdx.x;
    const int lane = tid & 31;
    const int warp = tid >> 5;            // 0..7

    extern __shared__ float smem[];
    char* smb = reinterpret_cast<char*>(smem);
    const uint32_t smem_base = smem_u32(smem);

    // ---- phase 1a: x -> A hi/lo bf16 images (swizzled 256B rows); zero V^T ----
    {
        const float2* xin = reinterpret_cast<const float2*>(x_g + (size_t)blk * (NTOK * CDIM));
        for (int e = tid; e < NTOK * 64; e += NTHREADS) {
            int row = e >> 6, kp = e & 63;
            float2 v = xin[e];
            uint32_t hp, lp; split2(v.x, v.y, hp, lp);
            uint32_t off = (uint32_t)row * 256 + (((kp >> 2) ^ (row & 7)) << 4) + (kp & 3) * 4;
            *reinterpret_cast<uint32_t*>(smb + RA_HI + off) = hp;
            *reinterpret_cast<uint32_t*>(smb + RA_LO + off) = lp;
        }
        float4* vz = reinterpret_cast<float4*>(smb + RVT_HI);   // hi+lo contiguous: 32768B
        for (int o = tid; o < 2048; o += NTHREADS) vz[o] = make_float4(0.f, 0.f, 0.f, 0.f);
    }
    __syncthreads();

    const int mt  = warp & 3;
    const int ng2 = warp >> 2;
    const int mtb = (mt < 3) ? mt * 16 : 33;

    // ---- QKV GEMM ----
    {
        uint32_t aH[8][4], aL[8][4];
        const int arow = mtb + (lane & 15);
        #pragma unroll
        for (int k = 0; k < 8; k++) {
            uint32_t off = (uint32_t)arow * 256 + (((2 * k + (lane >> 4)) ^ (arow & 7)) << 4);
            ldmx4(aH[k], smem_base + RA_HI + off);
            ldmx4(aL[k], smem_base + RA_LO + off);
        }

        const int r1 = mtb + (lane >> 2);
        const int r2 = r1 + 8;
        #pragma unroll
        for (int ck = 0; ck < 3; ck++) {
            #pragma unroll
            for (int nt8 = 0; nt8 < 8; nt8++) {
                const int ng4 = ng2 * 2 + (nt8 >> 2);
                const int nt4 = nt8 & 3;
                const uint4* fb = g_BqkvF + (size_t)(((ck * 4 + ng4) * 4 + nt4) * 256) + lane;
                float c[4] = {0.f, 0.f, 0.f, 0.f};
                #pragma unroll
                for (int kt2 = 0; kt2 < 4; kt2++) {
                    uint4 bhv = __ldg(fb + kt2 * 64);
                    uint4 blv = __ldg(fb + kt2 * 64 + 32);
                    mma16816(c, aH[2 * kt2],     bhv.x, bhv.y);
                    mma16816(c, aH[2 * kt2],     blv.x, blv.y);
                    mma16816(c, aL[2 * kt2],     bhv.x, bhv.y);
                    mma16816(c, aH[2 * kt2 + 1], bhv.z, bhv.w);
                    mma16816(c, aH[2 * kt2 + 1], blv.z, blv.w);
                    mma16816(c, aL[2 * kt2 + 1], bhv.z, bhv.w);
                }
                const int n0 = ng2 * 64 + nt8 * 8;
                const int coll = n0 + 2 * (lane & 3);
                float2 bias = __ldg(reinterpret_cast<const float2*>(qkv_b + ck * 128 + coll));
                float v0 = c[0] + bias.x, v1 = c[1] + bias.y;
                float v2 = c[2] + bias.x, v3 = c[3] + bias.y;
                if (ck < 2) {
                    const int bh = (ck == 0) ? RQ_HI : RK_HI;
                    const int bl = (ck == 0) ? RQ_LO : RK_LO;
                    const int chnk = ng2 * 8 + nt8;
                    uint32_t hp, lp;
                    split2(v0, v1, hp, lp);
                    uint32_t o1 = (uint32_t)r1 * 256 + (((chnk) ^ (r1 & 7)) << 4) + 4 * (lane & 3);
                    *reinterpret_cast<uint32_t*>(smb + bh + o1) = hp;
                    *reinterpret_cast<uint32_t*>(smb + bl + o1) = lp;
                    split2(v2, v3, hp, lp);
                    uint32_t o2 = (uint32_t)r2 * 256 + (((chnk) ^ (r2 & 7)) << 4) + 4 * (lane & 3);
                    *reinterpret_cast<uint32_t*>(smb + bh + o2) = hp;
                    *reinterpret_cast<uint32_t*>(smb + bl + o2) = lp;
                } else {
                    // V transposed: VT[channel][token], 128B swizzled rows, scalar bf16 stores
                    #pragma unroll
                    for (int q = 0; q < 4; q++) {
                        float val = (q == 0) ? v0 : (q == 1) ? v1 : (q == 2) ? v2 : v3;
                        int tok = (q < 2) ? r1 : r2;
                        int cc  = coll + (q & 1);
                        __nv_bfloat16 hb = __float2bfloat16(val);
                        __nv_bfloat16 lb = __float2bfloat16(val - __bfloat162float(hb));
                        uint32_t off = (uint32_t)cc * 128 + ((((tok >> 3)) ^ (cc & 7)) << 4) + ((tok * 2) & 15);
                        *reinterpret_cast<unsigned short*>(smb + RVT_HI + off) = __bfloat16_as_ushort(hb);
                        *reinterpret_cast<unsigned short*>(smb + RVT_LO + off) = __bfloat16_as_ushort(lb);
                    }
                }
            }
        }
    }
    __syncthreads();

    // ---- S = Q @ K^T per (head, m-tile); fragments kept in registers ----
    float cS[2][7][4];
    #pragma unroll
    for (int u = 0; u < 2; u++) {
        const int uid = warp * 2 + u;
        const int h   = uid >> 2;
        const int mtu = uid & 3;
        const int mtbu = (mtu < 3) ? mtu * 16 : 33;
        const int arow = mtbu + (lane & 15);

        uint32_t qH[2][4], qL[2][4];
        #pragma unroll
        for (int ks = 0; ks < 2; ks++) {
            uint32_t off = (uint32_t)arow * 256 + (((4 * h + 2 * ks + (lane >> 4)) ^ (arow & 7)) << 4);
            ldmx4(qH[ks], smem_base + RQ_HI + off);
            ldmx4(qL[ks], smem_base + RQ_LO + off);
        }
        #pragma unroll
        for (int nt = 0; nt < 7; nt++) {
            const int krow = nt * 8 + (lane & 7);
            uint32_t koff = (uint32_t)krow * 256 + (((4 * h + ((lane >> 3) & 3)) ^ (krow & 7)) << 4);
            uint32_t bH[4], bL[4];
            ldmx4(bH, smem_base + RK_HI + koff);
            ldmx4(bL, smem_base + RK_LO + koff);
            float* c = cS[u][nt];
            c[0] = c[1] = c[2] = c[3] = 0.f;
            mma16816(c, qH[0], bH[0], bH[1]);
            mma16816(c, qH[0], bL[0], bL[1]);
            mma16816(c, qL[0], bH[0], bH[1]);
            mma16816(c, qH[1], bH[2], bH[3]);
            mma16816(c, qH[1], bL[2], bL[3]);
            mma16816(c, qL[1], bH[2], bH[3]);
        }
    }
    __syncthreads();   // all Q/K reads done; P may now overwrite RA/RQ

    // ---- softmax in registers -> P bf16 hi/lo images ----
    {
        const float scale = 0.17677669529663687f;   // 1/sqrt(32)
        #pragma unroll
        for (int u = 0; u < 2; u++) {
            const int uid = warp * 2 + u;
            const int h   = uid >> 2;
            const int mtu = uid & 3;
            const int mtbu = (mtu < 3) ? mtu * 16 : 33;
            const int r1u = mtbu + (lane >> 2);
            const int r2u = r1u + 8;
            const float* cb1 = g_comb2 + (((size_t)(wi * NHEADS + h) * NTOK) + r1u) * 64 + 2 * (lane & 3);
            const float* cb2 = g_comb2 + (((size_t)(wi * NHEADS + h) * NTOK) + r2u) * 64 + 2 * (lane & 3);

            float e0[7], e1[7], e2[7], e3[7];
            float s0 = 0.f, s1 = 0.f;
            #pragma unroll
            for (int nt = 0; nt < 7; nt++) {
                float2 b1 = __ldg(reinterpret_cast<const float2*>(cb1 + nt * 8));
                float2 b2 = __ldg(reinterpret_cast<const float2*>(cb2 + nt * 8));
                float a0 = __expf(fmaf(cS[u][nt][0], scale, b1.x));
                float a1 = __expf(fmaf(cS[u][nt][1], scale, b1.y));
                float a2 = __expf(fmaf(cS[u][nt][2], scale, b2.x));
                float a3 = __expf(fmaf(cS[u][nt][3], scale, b2.y));
                if (nt == 6) {
                    bool v0 = ((lane & 3) == 0);    // only j=48 valid
                    a0 = v0 ? a0 : 0.f;  a1 = 0.f;
                    a2 = v0 ? a2 : 0.f;  a3 = 0.f;
                }
                e0[nt] = a0; e1[nt] = a1; e2[nt] = a2; e3[nt] = a3;
                s0 += a0 + a1;  s1 += a2 + a3;
            }
            s0 += __shfl_xor_sync(0xffffffffu, s0, 1);
            s0 += __shfl_xor_sync(0xffffffffu, s0, 2);
            s1 += __shfl_xor_sync(0xffffffffu, s1, 1);
            s1 += __shfl_xor_sync(0xffffffffu, s1, 2);
            float i0 = 1.0f / s0, i1 = 1.0f / s1;

            #pragma unroll
            for (int nt = 0; nt < 7; nt++) {
                uint32_t hp, lp;
                split2(e0[nt] * i0, e1[nt] * i0, hp, lp);
                uint32_t o1 = (uint32_t)r1u * 128 + ((nt ^ (r1u & 7)) << 4) + 4 * (lane & 3);
                *reinterpret_cast<uint32_t*>(smb + P_HI(h) + o1) = hp;
                *reinterpret_cast<uint32_t*>(smb + P_LO(h) + o1) = lp;
                split2(e2[nt] * i1, e3[nt] * i1, hp, lp);
                uint32_t o2 = (uint32_t)r2u * 128 + ((nt ^ (r2u & 7)) << 4) + 4 * (lane & 3);
                *reinterpret_cast<uint32_t*>(smb + P_HI(h) + o2) = hp;
                *reinterpret_cast<uint32_t*>(smb + P_LO(h) + o2) = lp;
            }
            // zero pad chunk 7 (j 56..63) so PV reads finite values
            uint32_t z1 = (uint32_t)r1u * 128 + ((7 ^ (r1u & 7)) << 4) + 4 * (lane & 3);
            uint32_t z2 = (uint32_t)r2u * 128 + ((7 ^ (r2u & 7)) << 4) + 4 * (lane & 3);
            *reinterpret_cast<uint32_t*>(smb + P_HI(h) + z1) = 0u;
            *reinterpret_cast<uint32_t*>(smb + P_LO(h) + z1) = 0u;
            *reinterpret_cast<uint32_t*>(smb + P_HI(h) + z2) = 0u;
            *reinterpret_cast<uint32_t*>(smb + P_LO(h) + z2) = 0u;
        }
    }
    __syncthreads();

    // ---- O = P @ V via mma; epilogue writes A' (proj A-operand) images ----
    #pragma unroll
    for (int u = 0; u < 2; u++) {
        const int uid = warp * 2 + u;
        const int h   = uid >> 2;
        const int mtu = uid & 3;
        const int mtbu = (mtu < 3) ? mtu * 16 : 33;
        const int arow = mtbu + (lane & 15);

        uint32_t pH[4][4], pL[4][4];
        #pragma unroll
        for (int ks = 0; ks < 4; ks++) {
            uint32_t off = (uint32_t)arow * 128 + (((2 * ks + (lane >> 4)) ^ (arow & 7)) << 4);
            ldmx4(pH[ks], smem_base + P_HI(h) + off);
            ldmx4(pL[ks], smem_base + P_LO(h) + off);
        }
        const int r1u = mtbu + (lane >> 2);
        const int r2u = r1u + 8;

        #pragma unroll
        for (int nt = 0; nt < 4; nt++) {
            const int vrow = 32 * h + nt * 8 + (lane & 7);
            uint32_t vo0 = (uint32_t)vrow * 128 + (((((lane >> 3) & 3)) ^ (vrow & 7)) << 4);
            uint32_t vo1 = (uint32_t)vrow * 128 + (((4 + ((lane >> 3) & 3)) ^ (vrow & 7)) << 4);
            uint32_t vH0[4], vH1[4], vL0[4], vL1[4];
            ldmx4(vH0, smem_base + RVT_HI + vo0);
            ldmx4(vH1, smem_base + RVT_HI + vo1);
            ldmx4(vL0, smem_base + RVT_LO + vo0);
            ldmx4(vL1, smem_base + RVT_LO + vo1);

            float c[4] = {0.f, 0.f, 0.f, 0.f};
            mma16816(c, pH[0], vH0[0], vH0[1]);
            mma16816(c, pH[0], vL0[0], vL0[1]);
            mma16816(c, pL[0], vH0[0], vH0[1]);
            mma16816(c, pH[1], vH0[2], vH0[3]);
            mma16816(c, pH[1], vL0[2], vL0[3]);
            mma16816(c, pL[1], vH0[2], vH0[3]);
            mma16816(c, pH[2], vH1[0], vH1[1]);
            mma16816(c, pH[2], vL1[0], vL1[1]);
            mma16816(c, pL[2], vH1[0], vH1[1]);
            mma16816(c, pH[3], vH1[2], vH1[3]);
            mma16816(c, pH[3], vL1[2], vL1[3]);
            mma16816(c, pL[3], vH1[2], vH1[3]);

            // store O frag -> A' images (K-major, 256B swizzled); channel chunk = 4h+nt
            const int chnk = 4 * h + nt;
            uint32_t hp, lp;
            split2(c[0], c[1], hp, lp);
            uint32_t o1 = (uint32_t)r1u * 256 + ((chnk ^ (r1u & 7)) << 4) + 4 * (lane & 3);
            *reinterpret_cast<uint32_t*>(smb + AP_HI + o1) = hp;
            *reinterpret_cast<uint32_t*>(smb + AP_LO + o1) = lp;
            split2(c[2], c[3], hp, lp);
            uint32_t o2 = (uint32_t)r2u * 256 + ((chnk ^ (r2u & 7)) << 4) + 4 * (lane & 3);
            *reinterpret_cast<uint32_t*>(smb + AP_HI + o2) = hp;
            *reinterpret_cast<uint32_t*>(smb + AP_LO + o2) = lp;
        }
    }
    __syncthreads();

    // ---- proj via mma, fragment-direct B; output -> global ----
    {
        uint32_t oH[8][4], oL[8][4];
        const int arow = mtb + (lane & 15);
        #pragma unroll
        for (int k = 0; k < 8; k++) {
            uint32_t off = (uint32_t)arow * 256 + (((2 * k + (lane >> 4)) ^ (arow & 7)) << 4);
            ldmx4(oH[k], smem_base + AP_HI + off);
            ldmx4(oL[k], smem_base + AP_LO + off);
        }
        const int r1 = mtb + (lane >> 2);
        const int r2 = r1 + 8;
        float* outp = out_g + (size_t)blk * (NTOK * CDIM);
        #pragma unroll
        for (int nt8 = 0; nt8 < 8; nt8++) {
            const int ng4 = ng2 * 2 + (nt8 >> 2);
            const int nt4 = nt8 & 3;
            const uint4* fb = g_BprojF + (size_t)((ng4 * 4 + nt4) * 256) + lane;
            float c[4] = {0.f, 0.f, 0.f, 0.f};
            #pragma unroll
            for (int kt2 = 0; kt2 < 4; kt2++) {
                uint4 bhv = __ldg(fb + kt2 * 64);
                uint4 blv = __ldg(fb + kt2 * 64 + 32);
                mma16816(c, oH[2 * kt2],     bhv.x, bhv.y);
                mma16816(c, oH[2 * kt2],     blv.x, blv.y);
                mma16816(c, oL[2 * kt2],     bhv.x, bhv.y);
                mma16816(c, oH[2 * kt2 + 1], bhv.z, bhv.w);
                mma16816(c, oH[2 * kt2 + 1], blv.z, blv.w);
                mma16816(c, oL[2 * kt2 + 1], bhv.z, bhv.w);
            }
            const int n0 = ng2 * 64 + nt8 * 8;
            const int coll = n0 + 2 * (lane & 3);
            float2 bias = __ldg(reinterpret_cast<const float2*>(proj_b + coll));
            *reinterpret_cast<float2*>(outp + r1 * CDIM + coll) = make_float2(c[0] + bias.x, c[1] + bias.y);
            *reinterpret_cast<float2*>(outp + r2 * CDIM + coll) = make_float2(c[2] + bias.x, c[3] + bias.y);
        }
    }
}

extern "C" void kernel_launch(void* const* d_in, const int* in_sizes, int n_in,
                              void* d_out, int out_size) {
    const float* x      = (const float*)d_in[0];
    const float* mask   = (const float*)d_in[1];
    const float* qkv_w  = (const float*)d_in[2];
    const float* qkv_b  = (const float*)d_in[3];
    const float* proj_w = (const float*)d_in[4];
    const float* proj_b = (const float*)d_in[5];
    const float* rel    = (const float*)d_in[6];
    float* out = (float*)d_out;

    (void)in_sizes; (void)n_in; (void)out_size;

    cudaFuncSetAttribute(swin_mma_kernel,
                         cudaFuncAttributeMaxDynamicSharedMemorySize, SMEM_TOTAL_B);

    swin_prol_kernel<<<COMB_BLKS + 64, 256>>>(rel, mask, qkv_w, proj_w);
    swin_mma_kernel<<<NBLK, NTHREADS, SMEM_TOTAL_B>>>(x, qkv_b, proj_b, out);
}

// round 12
// speedup vs baseline: 2.0960x; 1.0361x over previous
#include <cuda_runtime.h>
#include <cuda_bf16.h>
#include <math.h>
#include <stdint.h>

#define NHEADS   4
#define WIN      7
#define NTOK     49
#define CDIM     128
#define NWIN     64
#define NBLK     2048
#define NTHREADS 256

// ---------------- mma.sync helpers ----------------
__device__ __forceinline__ uint32_t smem_u32(const void* p) {
    uint32_t a;
    asm("{ .reg .u64 t; cvta.to.shared.u64 t, %1; cvt.u32.u64 %0, t; }" : "=r"(a) : "l"(p));
    return a;
}
__device__ __forceinline__ void ldmx4(uint32_t* d, uint32_t addr) {
    asm volatile("ldmatrix.sync.aligned.m8n8.x4.shared.b16 {%0,%1,%2,%3}, [%4];"
        : "=r"(d[0]), "=r"(d[1]), "=r"(d[2]), "=r"(d[3]) : "r"(addr));
}
__device__ __forceinline__ void mma16816(float* c, const uint32_t* a, uint32_t b0, uint32_t b1) {
    asm volatile("mma.sync.aligned.m16n8k16.row.col.f32.bf16.bf16.f32 "
        "{%0,%1,%2,%3}, {%4,%5,%6,%7}, {%8,%9}, {%0,%1,%2,%3};"
        : "+f"(c[0]), "+f"(c[1]), "+f"(c[2]), "+f"(c[3])
        : "r"(a[0]), "r"(a[1]), "r"(a[2]), "r"(a[3]), "r"(b0), "r"(b1));
}
__device__ __forceinline__ void split2(float x0, float x1, uint32_t &hp, uint32_t &lp) {
    __nv_bfloat16 h0 = __float2bfloat16(x0);
    __nv_bfloat16 h1 = __float2bfloat16(x1);
    __nv_bfloat16 l0 = __float2bfloat16(x0 - __bfloat162float(h0));
    __nv_bfloat16 l1 = __float2bfloat16(x1 - __bfloat162float(h1));
    hp = ((uint32_t)__bfloat16_as_ushort(h1) << 16) | __bfloat16_as_ushort(h0);
    lp = ((uint32_t)__bfloat16_as_ushort(l1) << 16) | __bfloat16_as_ushort(l0);
}

// ---------------- smem regions (bytes); all images XOR-swizzled ----------------
// RA: x imgs (phase1) -> A' (O) imgs for proj (PV epilogue overlay).
#define RA_HI   0
#define RA_LO   12544
#define RQ_HI   25088
#define RQ_LO   37632
#define RK_HI   50176
#define RK_LO   64512
#define RVT_HI  78848
#define RVT_LO  95232
#define SMEM_TOTAL_B 111616
#define AP_HI   RA_HI
#define AP_LO   RA_LO

// ---------------- device globals ----------------
__device__ float g_comb2[NWIN * NHEADS * NTOK * 64];   // padded to 64 cols
__device__ uint4 g_BqkvF[12288];
__device__ uint4 g_BprojF[4096];

__device__ __forceinline__ uint32_t pack_split(float w0, float w1, int img) {
    __nv_bfloat16 h0 = __float2bfloat16(w0);
    __nv_bfloat16 h1 = __float2bfloat16(w1);
    if (img == 0)
        return ((uint32_t)__bfloat16_as_ushort(h1) << 16) | __bfloat16_as_ushort(h0);
    __nv_bfloat16 l0 = __float2bfloat16(w0 - __bfloat162float(h0));
    __nv_bfloat16 l1 = __float2bfloat16(w1 - __bfloat162float(h1));
    return ((uint32_t)__bfloat16_as_ushort(l1) << 16) | __bfloat16_as_ushort(l0);
}

#define COMB_BLKS 2401
__global__ void swin_prol_kernel(const float* __restrict__ rel_table,
                                 const float* __restrict__ mask,
                                 const float* __restrict__ qkv_w,
                                 const float* __restrict__ proj_w) {
    if (blockIdx.x < COMB_BLKS) {
        int e = blockIdx.x * blockDim.x + threadIdx.x;
        if (e >= NWIN * NHEADS * NTOK * NTOK) return;
        int j = e % NTOK;
        int t = e / NTOK;
        int i = t % NTOK;  t /= NTOK;
        int h = t % NHEADS;
        int w = t / NHEADS;
        int yi = i / WIN, xi = i % WIN, yj = j / WIN, xj = j % WIN;
        int r = (yi - yj + WIN - 1) * (2 * WIN - 1) + (xi - xj + WIN - 1);
        g_comb2[(((w * NHEADS + h) * NTOK) + i) * 64 + j] =
            rel_table[r * NHEADS + h] + mask[(w * NTOK + i) * NTOK + j];
    } else {
        int e = (blockIdx.x - COMB_BLKS) * blockDim.x + threadIdx.x;
        if (e >= 16384) return;
        bool isproj = (e >= 12288);
        int idx = isproj ? (e - 12288) : e;
        int lane = idx & 31;
        int img  = (idx >> 5) & 1;
        int kt2  = (idx >> 6) & 3;
        int nt   = (idx >> 8) & 3;
        int ng   = (idx >> 10) & 3;
        int chunk = isproj ? 0 : (idx >> 12);
        int n = ng * 32 + nt * 8 + (lane >> 2);
        uint32_t r[4];
        #pragma unroll
        for (int m = 0; m < 4; m++) {
            int k = kt2 * 32 + m * 8 + 2 * (lane & 3);
            float w0, w1;
            if (isproj) { w0 = proj_w[k * 128 + n];              w1 = proj_w[(k + 1) * 128 + n]; }
            else        { w0 = qkv_w[k * 384 + chunk * 128 + n]; w1 = qkv_w[(k + 1) * 384 + chunk * 128 + n]; }
            r[m] = pack_split(w0, w1, img);
        }
        uint4 v = make_uint4(r[0], r[1], r[2], r[3]);
        if (isproj) g_BprojF[idx] = v; else g_BqkvF[idx] = v;
    }
}

__global__ __launch_bounds__(NTHREADS, 2)
void swin_mma_kernel(const float* __restrict__ x_g,
                     const float* __restrict__ qkv_b,
                     const float* __restrict__ proj_b,
                     float* __restrict__ out_g) {
    const int blk  = blockIdx.x;
    const int wi   = blk & (NWIN - 1);
    const int tid  = threadIdx.x;
    const int lane = tid & 31;
    const int warp = tid >> 5;            // 0..7

    extern __shared__ float smem[];
    char* smb = reinterpret_cast<char*>(smem);
    const uint32_t smem_base = smem_u32(smem);

    // ---- phase 1a: x -> RA hi/lo bf16 images (swizzled 256B rows); zero V^T ----
    {
        const float2* xin = reinterpret_cast<const float2*>(x_g + (size_t)blk * (NTOK * CDIM));
        for (int e = tid; e < NTOK * 64; e += NTHREADS) {
            int row = e >> 6, kp = e & 63;
            float2 v = xin[e];
            uint32_t hp, lp; split2(v.x, v.y, hp, lp);
            uint32_t off = (uint32_t)row * 256 + (((kp >> 2) ^ (row & 7)) << 4) + (kp & 3) * 4;
            *reinterpret_cast<uint32_t*>(smb + RA_HI + off) = hp;
            *reinterpret_cast<uint32_t*>(smb + RA_LO + off) = lp;
        }
        float4* vz = reinterpret_cast<float4*>(smb + RVT_HI);   // hi+lo contiguous 32768B
        for (int o = tid; o < 2048; o += NTHREADS) vz[o] = make_float4(0.f, 0.f, 0.f, 0.f);
    }
    __syncthreads();

    const int mt  = warp & 3;
    const int ng2 = warp >> 2;
    const int mtb = (mt < 3) ? mt * 16 : 33;

    // ---- QKV GEMM ----
    {
        uint32_t aH[8][4], aL[8][4];
        const int arow = mtb + (lane & 15);
        #pragma unroll
        for (int k = 0; k < 8; k++) {
            uint32_t off = (uint32_t)arow * 256 + (((2 * k + (lane >> 4)) ^ (arow & 7)) << 4);
            ldmx4(aH[k], smem_base + RA_HI + off);
            ldmx4(aL[k], smem_base + RA_LO + off);
        }

        const int r1 = mtb + (lane >> 2);
        const int r2 = r1 + 8;
        #pragma unroll
        for (int ck = 0; ck < 3; ck++) {
            #pragma unroll
            for (int nt8 = 0; nt8 < 8; nt8++) {
                const int ng4 = ng2 * 2 + (nt8 >> 2);
                const int nt4 = nt8 & 3;
                const uint4* fb = g_BqkvF + (size_t)(((ck * 4 + ng4) * 4 + nt4) * 256) + lane;
                float c[4] = {0.f, 0.f, 0.f, 0.f};
                #pragma unroll
                for (int kt2 = 0; kt2 < 4; kt2++) {
                    uint4 bhv = __ldg(fb + kt2 * 64);
                    uint4 blv = __ldg(fb + kt2 * 64 + 32);
                    mma16816(c, aH[2 * kt2],     bhv.x, bhv.y);
                    mma16816(c, aH[2 * kt2],     blv.x, blv.y);
                    mma16816(c, aL[2 * kt2],     bhv.x, bhv.y);
                    mma16816(c, aH[2 * kt2 + 1], bhv.z, bhv.w);
                    mma16816(c, aH[2 * kt2 + 1], blv.z, blv.w);
                    mma16816(c, aL[2 * kt2 + 1], bhv.z, bhv.w);
                }
                const int n0 = ng2 * 64 + nt8 * 8;
                const int coll = n0 + 2 * (lane & 3);
                float2 bias = __ldg(reinterpret_cast<const float2*>(qkv_b + ck * 128 + coll));
                float v0 = c[0] + bias.x, v1 = c[1] + bias.y;
                float v2 = c[2] + bias.x, v3 = c[3] + bias.y;
                if (ck < 2) {
                    const int bh = (ck == 0) ? RQ_HI : RK_HI;
                    const int bl = (ck == 0) ? RQ_LO : RK_LO;
                    const int chnk = ng2 * 8 + nt8;
                    uint32_t hp, lp;
                    split2(v0, v1, hp, lp);
                    uint32_t o1 = (uint32_t)r1 * 256 + (((chnk) ^ (r1 & 7)) << 4) + 4 * (lane & 3);
                    *reinterpret_cast<uint32_t*>(smb + bh + o1) = hp;
                    *reinterpret_cast<uint32_t*>(smb + bl + o1) = lp;
                    split2(v2, v3, hp, lp);
                    uint32_t o2 = (uint32_t)r2 * 256 + (((chnk) ^ (r2 & 7)) << 4) + 4 * (lane & 3);
                    *reinterpret_cast<uint32_t*>(smb + bh + o2) = hp;
                    *reinterpret_cast<uint32_t*>(smb + bl + o2) = lp;
                } else {
                    // V transposed: VT[channel][token], 128B swizzled rows, scalar bf16 stores
                    #pragma unroll
                    for (int q = 0; q < 4; q++) {
                        float val = (q == 0) ? v0 : (q == 1) ? v1 : (q == 2) ? v2 : v3;
                        int tok = (q < 2) ? r1 : r2;
                        int cc  = coll + (q & 1);
                        __nv_bfloat16 hb = __float2bfloat16(val);
                        __nv_bfloat16 lb = __float2bfloat16(val - __bfloat162float(hb));
                        uint32_t off = (uint32_t)cc * 128 + ((((tok >> 3)) ^ (cc & 7)) << 4) + ((tok * 2) & 15);
                        *reinterpret_cast<unsigned short*>(smb + RVT_HI + off) = __bfloat16_as_ushort(hb);
                        *reinterpret_cast<unsigned short*>(smb + RVT_LO + off) = __bfloat16_as_ushort(lb);
                    }
                }
            }
        }
    }
    __syncthreads();

    // ---- attention: per unit: S=QK^T -> softmax (regs) -> P frags (regs) -> PV -> A' ----
    {
        const float scale = 0.17677669529663687f;   // 1/sqrt(32)
        #pragma unroll
        for (int u = 0; u < 2; u++) {
            const int uid = warp * 2 + u;
            const int h   = uid >> 2;
            const int mtu = uid & 3;
            const int mtbu = (mtu < 3) ? mtu * 16 : 33;
            const int arow = mtbu + (lane & 15);
            const int r1u = mtbu + (lane >> 2);
            const int r2u = r1u + 8;

            // Q fragments
            uint32_t qH[2][4], qL[2][4];
            #pragma unroll
            for (int ks = 0; ks < 2; ks++) {
                uint32_t off = (uint32_t)arow * 256 + (((4 * h + 2 * ks + (lane >> 4)) ^ (arow & 7)) << 4);
                ldmx4(qH[ks], smem_base + RQ_HI + off);
                ldmx4(qL[ks], smem_base + RQ_LO + off);
            }
            // prefetch comb rows (in flight during S MMAs)
            const float* cb1 = g_comb2 + (((size_t)(wi * NHEADS + h) * NTOK) + r1u) * 64 + 2 * (lane & 3);
            const float* cb2 = g_comb2 + (((size_t)(wi * NHEADS + h) * NTOK) + r2u) * 64 + 2 * (lane & 3);
            float2 cv1[7], cv2[7];
            #pragma unroll
            for (int nt = 0; nt < 7; nt++) {
                cv1[nt] = __ldg(reinterpret_cast<const float2*>(cb1 + nt * 8));
                cv2[nt] = __ldg(reinterpret_cast<const float2*>(cb2 + nt * 8));
            }

            // S = Q K^T (hi/lo 3-term)
            float cS[7][4];
            #pragma unroll
            for (int nt = 0; nt < 7; nt++) {
                const int krow = nt * 8 + (lane & 7);
                uint32_t koff = (uint32_t)krow * 256 + (((4 * h + ((lane >> 3) & 3)) ^ (krow & 7)) << 4);
                uint32_t bH[4], bL[4];
                ldmx4(bH, smem_base + RK_HI + koff);
                ldmx4(bL, smem_base + RK_LO + koff);
                float* c = cS[nt];
                c[0] = c[1] = c[2] = c[3] = 0.f;
                mma16816(c, qH[0], bH[0], bH[1]);
                mma16816(c, qH[0], bL[0], bL[1]);
                mma16816(c, qL[0], bH[0], bH[1]);
                mma16816(c, qH[1], bH[2], bH[3]);
                mma16816(c, qH[1], bL[2], bL[3]);
                mma16816(c, qL[1], bH[2], bH[3]);
            }

            // softmax in registers (no max pass; logits tiny)
            float s0 = 0.f, s1 = 0.f;
            #pragma unroll
            for (int nt = 0; nt < 7; nt++) {
                float a0 = __expf(fmaf(cS[nt][0], scale, cv1[nt].x));
                float a1 = __expf(fmaf(cS[nt][1], scale, cv1[nt].y));
                float a2 = __expf(fmaf(cS[nt][2], scale, cv2[nt].x));
                float a3 = __expf(fmaf(cS[nt][3], scale, cv2[nt].y));
                if (nt == 6) {
                    bool v0 = ((lane & 3) == 0);    // only j=48 valid
                    a0 = v0 ? a0 : 0.f;  a1 = 0.f;
                    a2 = v0 ? a2 : 0.f;  a3 = 0.f;
                }
                cS[nt][0] = a0; cS[nt][1] = a1; cS[nt][2] = a2; cS[nt][3] = a3;
                s0 += a0 + a1;  s1 += a2 + a3;
            }
            s0 += __shfl_xor_sync(0xffffffffu, s0, 1);
            s0 += __shfl_xor_sync(0xffffffffu, s0, 2);
            s1 += __shfl_xor_sync(0xffffffffu, s1, 1);
            s1 += __shfl_xor_sync(0xffffffffu, s1, 2);
            float i0 = 1.0f / s0, i1 = 1.0f / s1;

            // pack P A-fragments (hi/lo) directly from registers
            uint32_t paH[4][4], paL[4][4];
            #pragma unroll
            for (int m = 0; m < 4; m++) {
                split2(cS[2 * m][0] * i0, cS[2 * m][1] * i0, paH[m][0], paL[m][0]);
                split2(cS[2 * m][2] * i1, cS[2 * m][3] * i1, paH[m][1], paL[m][1]);
                if (2 * m + 1 < 7) {
                    split2(cS[2 * m + 1][0] * i0, cS[2 * m + 1][1] * i0, paH[m][2], paL[m][2]);
                    split2(cS[2 * m + 1][2] * i1, cS[2 * m + 1][3] * i1, paH[m][3], paL[m][3]);
                } else {
                    paH[m][2] = paL[m][2] = 0u;
                    paH[m][3] = paL[m][3] = 0u;
                }
            }

            // O = P @ V; epilogue -> A' images (over dead RA)
            #pragma unroll
            for (int nt = 0; nt < 4; nt++) {
                const int vrow = 32 * h + nt * 8 + (lane & 7);
                uint32_t vo0 = (uint32_t)vrow * 128 + (((((lane >> 3) & 3)) ^ (vrow & 7)) << 4);
                uint32_t vo1 = (uint32_t)vrow * 128 + (((4 + ((lane >> 3) & 3)) ^ (vrow & 7)) << 4);
                uint32_t vH0[4], vH1[4], vL0[4], vL1[4];
                ldmx4(vH0, smem_base + RVT_HI + vo0);
                ldmx4(vH1, smem_base + RVT_HI + vo1);
                ldmx4(vL0, smem_base + RVT_LO + vo0);
                ldmx4(vL1, smem_base + RVT_LO + vo1);

                float c[4] = {0.f, 0.f, 0.f, 0.f};
                mma16816(c, paH[0], vH0[0], vH0[1]);
                mma16816(c, paH[0], vL0[0], vL0[1]);
                mma16816(c, paL[0], vH0[0], vH0[1]);
                mma16816(c, paH[1], vH0[2], vH0[3]);
                mma16816(c, paH[1], vL0[2], vL0[3]);
                mma16816(c, paL[1], vH0[2], vH0[3]);
                mma16816(c, paH[2], vH1[0], vH1[1]);
                mma16816(c, paH[2], vL1[0], vL1[1]);
                mma16816(c, paL[2], vH1[0], vH1[1]);
                mma16816(c, paH[3], vH1[2], vH1[3]);
                mma16816(c, paH[3], vL1[2], vL1[3]);
                mma16816(c, paL[3], vH1[2], vH1[3]);

                const int chnk = 4 * h + nt;
                uint32_t hp, lp;
                split2(c[0], c[1], hp, lp);
                uint32_t o1 = (uint32_t)r1u * 256 + ((chnk ^ (r1u & 7)) << 4) + 4 * (lane & 3);
                *reinterpret_cast<uint32_t*>(smb + AP_HI + o1) = hp;
                *reinterpret_cast<uint32_t*>(smb + AP_LO + o1) = lp;
                split2(c[2], c[3], hp, lp);
                uint32_t o2 = (uint32_t)r2u * 256 + ((chnk ^ (r2u & 7)) << 4) + 4 * (lane & 3);
                *reinterpret_cast<uint32_t*>(smb + AP_HI + o2) = hp;
                *reinterpret_cast<uint32_t*>(smb + AP_LO + o2) = lp;
            }
        }
    }
    __syncthreads();

    // ---- proj via mma, fragment-direct B; output -> global ----
    {
        uint32_t oH[8][4], oL[8][4];
        const int arow = mtb + (lane & 15);
        #pragma unroll
        for (int k = 0; k < 8; k++) {
            uint32_t off = (uint32_t)arow * 256 + (((2 * k + (lane >> 4)) ^ (arow & 7)) << 4);
            ldmx4(oH[k], smem_base + AP_HI + off);
            ldmx4(oL[k], smem_base + AP_LO + off);
        }
        const int r1 = mtb + (lane >> 2);
        const int r2 = r1 + 8;
        float* outp = out_g + (size_t)blk * (NTOK * CDIM);
        #pragma unroll
        for (int nt8 = 0; nt8 < 8; nt8++) {
            const int ng4 = ng2 * 2 + (nt8 >> 2);
            const int nt4 = nt8 & 3;
            const uint4* fb = g_BprojF + (size_t)((ng4 * 4 + nt4) * 256) + lane;
            float c[4] = {0.f, 0.f, 0.f, 0.f};
            #pragma unroll
            for (int kt2 = 0; kt2 < 4; kt2++) {
                uint4 bhv = __ldg(fb + kt2 * 64);
                uint4 blv = __ldg(fb + kt2 * 64 + 32);
                mma16816(c, oH[2 * kt2],     bhv.x, bhv.y);
                mma16816(c, oH[2 * kt2],     blv.x, blv.y);
                mma16816(c, oL[2 * kt2],     bhv.x, bhv.y);
                mma16816(c, oH[2 * kt2 + 1], bhv.z, bhv.w);
                mma16816(c, oH[2 * kt2 + 1], blv.z, blv.w);
                mma16816(c, oL[2 * kt2 + 1], bhv.z, bhv.w);
            }
            const int n0 = ng2 * 64 + nt8 * 8;
            const int coll = n0 + 2 * (lane & 3);
            float2 bias = __ldg(reinterpret_cast<const float2*>(proj_b + coll));
            *reinterpret_cast<float2*>(outp + r1 * CDIM + coll) = make_float2(c[0] + bias.x, c[1] + bias.y);
            *reinterpret_cast<float2*>(outp + r2 * CDIM + coll) = make_float2(c[2] + bias.x, c[3] + bias.y);
        }
    }
}

extern "C" void kernel_launch(void* const* d_in, const int* in_sizes, int n_in,
                              void* d_out, int out_size) {
    const float* x      = (const float*)d_in[0];
    const float* mask   = (const float*)d_in[1];
    const float* qkv_w  = (const float*)d_in[2];
    const float* qkv_b  = (const float*)d_in[3];
    const float* proj_w = (const float*)d_in[4];
    const float* proj_b = (const float*)d_in[5];
    const float* rel    = (const float*)d_in[6];
    float* out = (float*)d_out;

    (void)in_sizes; (void)n_in; (void)out_size;

    cudaFuncSetAttribute(swin_mma_kernel,
                         cudaFuncAttributeMaxDynamicSharedMemorySize, SMEM_TOTAL_B);

    swin_prol_kernel<<<COMB_BLKS + 64, 256>>>(rel, mask, qkv_w, proj_w);
    swin_mma_kernel<<<NBLK, NTHREADS, SMEM_TOTAL_B>>>(x, qkv_b, proj_b, out);
}

// round 14
// speedup vs baseline: 2.1836x; 1.0418x over previous
#include <cuda_runtime.h>
#include <cuda_bf16.h>
#include <math.h>
#include <stdint.h>

#define NHEADS   4
#define WIN      7
#define NTOK     49
#define CDIM     128
#define NWIN     64
#define NBLK     2048
#define NTHREADS 256

// ---------------- mma.sync helpers ----------------
__device__ __forceinline__ uint32_t smem_u32(const void* p) {
    uint32_t a;
    asm("{ .reg .u64 t; cvta.to.shared.u64 t, %1; cvt.u32.u64 %0, t; }" : "=r"(a) : "l"(p));
    return a;
}
__device__ __forceinline__ void ldmx4(uint32_t* d, uint32_t addr) {
    asm volatile("ldmatrix.sync.aligned.m8n8.x4.shared.b16 {%0,%1,%2,%3}, [%4];"
        : "=r"(d[0]), "=r"(d[1]), "=r"(d[2]), "=r"(d[3]) : "r"(addr));
}
__device__ __forceinline__ void ldmx4t(uint32_t* d, uint32_t addr) {
    asm volatile("ldmatrix.sync.aligned.m8n8.x4.trans.shared.b16 {%0,%1,%2,%3}, [%4];"
        : "=r"(d[0]), "=r"(d[1]), "=r"(d[2]), "=r"(d[3]) : "r"(addr));
}
__device__ __forceinline__ void mma16816(float* c, const uint32_t* a, uint32_t b0, uint32_t b1) {
    asm volatile("mma.sync.aligned.m16n8k16.row.col.f32.bf16.bf16.f32 "
        "{%0,%1,%2,%3}, {%4,%5,%6,%7}, {%8,%9}, {%0,%1,%2,%3};"
        : "+f"(c[0]), "+f"(c[1]), "+f"(c[2]), "+f"(c[3])
        : "r"(a[0]), "r"(a[1]), "r"(a[2]), "r"(a[3]), "r"(b0), "r"(b1));
}
__device__ __forceinline__ void split2(float x0, float x1, uint32_t &hp, uint32_t &lp) {
    __nv_bfloat16 h0 = __float2bfloat16(x0);
    __nv_bfloat16 h1 = __float2bfloat16(x1);
    __nv_bfloat16 l0 = __float2bfloat16(x0 - __bfloat162float(h0));
    __nv_bfloat16 l1 = __float2bfloat16(x1 - __bfloat162float(h1));
    hp = ((uint32_t)__bfloat16_as_ushort(h1) << 16) | __bfloat16_as_ushort(h0);
    lp = ((uint32_t)__bfloat16_as_ushort(l1) << 16) | __bfloat16_as_ushort(l0);
}

// ---------------- smem regions (bytes); XOR-swizzled 256B rows ----------------
// RA: x imgs (phase1) -> A' (O) imgs for proj.  RK: K imgs (56 rows).  RV: V imgs (64 rows).
#define RA_HI   0
#define RA_LO   12544
#define RK_HI   25088
#define RK_LO   39424
#define RV_HI   53760
#define RV_LO   70144
#define SMEM_TOTAL_B 86528
#define AP_HI   RA_HI
#define AP_LO   RA_LO

// ---------------- device globals ----------------
__device__ float g_comb2[NWIN * NHEADS * NTOK * 64];   // padded to 64 cols
__device__ uint4 g_BqkvF[12288];
__device__ uint4 g_BprojF[4096];

__device__ __forceinline__ uint32_t pack_split(float w0, float w1, int img) {
    __nv_bfloat16 h0 = __float2bfloat16(w0);
    __nv_bfloat16 h1 = __float2bfloat16(w1);
    if (img == 0)
        return ((uint32_t)__bfloat16_as_ushort(h1) << 16) | __bfloat16_as_ushort(h0);
    __nv_bfloat16 l0 = __float2bfloat16(w0 - __bfloat162float(h0));
    __nv_bfloat16 l1 = __float2bfloat16(w1 - __bfloat162float(h1));
    return ((uint32_t)__bfloat16_as_ushort(l1) << 16) | __bfloat16_as_ushort(l0);
}

#define COMB_BLKS 2401
__global__ void swin_prol_kernel(const float* __restrict__ rel_table,
                                 const float* __restrict__ mask,
                                 const float* __restrict__ qkv_w,
                                 const float* __restrict__ proj_w) {
    if (blockIdx.x < COMB_BLKS) {
        int e = blockIdx.x * blockDim.x + threadIdx.x;
        if (e >= NWIN * NHEADS * NTOK * NTOK) return;
        int j = e % NTOK;
        int t = e / NTOK;
        int i = t % NTOK;  t /= NTOK;
        int h = t % NHEADS;
        int w = t / NHEADS;
        int yi = i / WIN, xi = i % WIN, yj = j / WIN, xj = j % WIN;
        int r = (yi - yj + WIN - 1) * (2 * WIN - 1) + (xi - xj + WIN - 1);
        g_comb2[(((w * NHEADS + h) * NTOK) + i) * 64 + j] =
            rel_table[r * NHEADS + h] + mask[(w * NTOK + i) * NTOK + j];
    } else {
        int e = (blockIdx.x - COMB_BLKS) * blockDim.x + threadIdx.x;
        if (e >= 16384) return;
        bool isproj = (e >= 12288);
        int idx = isproj ? (e - 12288) : e;
        int lane = idx & 31;
        int img  = (idx >> 5) & 1;
        int kt2  = (idx >> 6) & 3;
        int nt   = (idx >> 8) & 3;
        int ng   = (idx >> 10) & 3;
        int chunk = isproj ? 0 : (idx >> 12);
        int n = ng * 32 + nt * 8 + (lane >> 2);
        uint32_t r[4];
        #pragma unroll
        for (int m = 0; m < 4; m++) {
            int k = kt2 * 32 + m * 8 + 2 * (lane & 3);
            float w0, w1;
            if (isproj) { w0 = proj_w[k * 128 + n];              w1 = proj_w[(k + 1) * 128 + n]; }
            else        { w0 = qkv_w[k * 384 + chunk * 128 + n]; w1 = qkv_w[(k + 1) * 384 + chunk * 128 + n]; }
            r[m] = pack_split(w0, w1, img);
        }
        uint4 v = make_uint4(r[0], r[1], r[2], r[3]);
        if (isproj) g_BprojF[idx] = v; else g_BqkvF[idx] = v;
    }
}

__global__ __launch_bounds__(NTHREADS, 2)
void swin_mma_kernel(const float* __restrict__ x_g,
                     const float* __restrict__ qkv_b,
                     const float* __restrict__ proj_b,
                     float* __restrict__ out_g) {
    const int blk  = blockIdx.x;
    const int wi   = blk & (NWIN - 1);
    const int tid  = threadIdx.x;
    const int lane = tid & 31;
    const int warp = tid >> 5;            // 0..7

    extern __shared__ float smem[];
    char* smb = reinterpret_cast<char*>(smem);
    const uint32_t smem_base = smem_u32(smem);

    // ---- phase 1a: x -> RA hi/lo bf16 images; zero V rows 49..63 (both imgs) ----
    {
        const float2* xin = reinterpret_cast<const float2*>(x_g + (size_t)blk * (NTOK * CDIM));
        for (int e = tid; e < NTOK * 64; e += NTHREADS) {
            int row = e >> 6, kp = e & 63;
            float2 v = xin[e];
            uint32_t hp, lp; split2(v.x, v.y, hp, lp);
            uint32_t off = (uint32_t)row * 256 + (((kp >> 2) ^ (row & 7)) << 4) + (kp & 3) * 4;
            *reinterpret_cast<uint32_t*>(smb + RA_HI + off) = hp;
            *reinterpret_cast<uint32_t*>(smb + RA_LO + off) = lp;
        }
        for (int o = tid; o < 480; o += NTHREADS) {   // 15 rows x 16 f4 x 2 imgs
            int img = o / 240, rem = o % 240;
            int r = 49 + rem / 16, c = rem % 16;
            *reinterpret_cast<float4*>(smb + RV_HI + img * 16384 + r * 256 + c * 16) =
                make_float4(0.f, 0.f, 0.f, 0.f);
        }
    }
    __syncthreads();

    const int mt  = warp & 3;
    const int ng2 = warp >> 2;
    const int mtb = (mt < 3) ? mt * 16 : 33;
    const int r1  = mtb + (lane >> 2);
    const int r2  = r1 + 8;

    // ---- QKV GEMM: order K, V, Q (Q result stays in registers) ----
    float vQ[8][4];
    {
        uint32_t aH[8][4], aL[8][4];
        const int arow = mtb + (lane & 15);
        #pragma unroll
        for (int k = 0; k < 8; k++) {
            uint32_t off = (uint32_t)arow * 256 + (((2 * k + (lane >> 4)) ^ (arow & 7)) << 4);
            ldmx4(aH[k], smem_base + RA_HI + off);
            ldmx4(aL[k], smem_base + RA_LO + off);
        }

        #pragma unroll
        for (int ckx = 0; ckx < 3; ckx++) {
            const int ck = (ckx == 0) ? 1 : (ckx == 1) ? 2 : 0;   // K, V, Q
            #pragma unroll
            for (int nt8 = 0; nt8 < 8; nt8++) {
                const int ng4 = ng2 * 2 + (nt8 >> 2);
                const int nt4 = nt8 & 3;
                const uint4* fb = g_BqkvF + (size_t)(((ck * 4 + ng4) * 4 + nt4) * 256) + lane;
                float c[4] = {0.f, 0.f, 0.f, 0.f};
                #pragma unroll
                for (int kt2 = 0; kt2 < 4; kt2++) {
                    uint4 bhv = __ldg(fb + kt2 * 64);
                    uint4 blv = __ldg(fb + kt2 * 64 + 32);
                    mma16816(c, aH[2 * kt2],     bhv.x, bhv.y);
                    mma16816(c, aH[2 * kt2],     blv.x, blv.y);
                    mma16816(c, aL[2 * kt2],     bhv.x, bhv.y);
                    mma16816(c, aH[2 * kt2 + 1], bhv.z, bhv.w);
                    mma16816(c, aH[2 * kt2 + 1], blv.z, blv.w);
                    mma16816(c, aL[2 * kt2 + 1], bhv.z, bhv.w);
                }
                const int n0 = ng2 * 64 + nt8 * 8;
                const int coll = n0 + 2 * (lane & 3);
                float2 bias = __ldg(reinterpret_cast<const float2*>(qkv_b + ck * 128 + coll));
                float v0 = c[0] + bias.x, v1 = c[1] + bias.y;
                float v2 = c[2] + bias.x, v3 = c[3] + bias.y;
                if (ck == 0) {
                    vQ[nt8][0] = v0; vQ[nt8][1] = v1; vQ[nt8][2] = v2; vQ[nt8][3] = v3;
                } else {
                    const int bh = (ck == 1) ? RK_HI : RV_HI;
                    const int bl = (ck == 1) ? RK_LO : RV_LO;
                    const int chnk = ng2 * 8 + nt8;
                    uint32_t hp, lp;
                    split2(v0, v1, hp, lp);
                    uint32_t o1 = (uint32_t)r1 * 256 + ((chnk ^ (r1 & 7)) << 4) + 4 * (lane & 3);
                    *reinterpret_cast<uint32_t*>(smb + bh + o1) = hp;
                    *reinterpret_cast<uint32_t*>(smb + bl + o1) = lp;
                    split2(v2, v3, hp, lp);
                    uint32_t o2 = (uint32_t)r2 * 256 + ((chnk ^ (r2 & 7)) << 4) + 4 * (lane & 3);
                    *reinterpret_cast<uint32_t*>(smb + bh + o2) = hp;
                    *reinterpret_cast<uint32_t*>(smb + bl + o2) = lp;
                }
            }
        }
    }
    __syncthreads();

    // ---- attention: unit u -> head h = 2*ng2+u, rows = this warp's mtb tile ----
    {
        const float scale = 0.17677669529663687f;   // 1/sqrt(32)
        #pragma unroll
        for (int u = 0; u < 2; u++) {
            const int h = 2 * ng2 + u;

            // pack Q A-fragments (hi/lo) straight from QKV C-frags
            uint32_t qH[2][4], qL[2][4];
            #pragma unroll
            for (int ks = 0; ks < 2; ks++) {
                const int t0 = 4 * u + 2 * ks, t1 = t0 + 1;
                split2(vQ[t0][0], vQ[t0][1], qH[ks][0], qL[ks][0]);
                split2(vQ[t0][2], vQ[t0][3], qH[ks][1], qL[ks][1]);
                split2(vQ[t1][0], vQ[t1][1], qH[ks][2], qL[ks][2]);
                split2(vQ[t1][2], vQ[t1][3], qH[ks][3], qL[ks][3]);
            }

            // prefetch comb rows
            const float* cb1 = g_comb2 + (((size_t)(wi * NHEADS + h) * NTOK) + r1) * 64 + 2 * (lane & 3);
            const float* cb2 = g_comb2 + (((size_t)(wi * NHEADS + h) * NTOK) + r2) * 64 + 2 * (lane & 3);
            float2 cv1[7], cv2[7];
            #pragma unroll
            for (int nt = 0; nt < 7; nt++) {
                cv1[nt] = __ldg(reinterpret_cast<const float2*>(cb1 + nt * 8));
                cv2[nt] = __ldg(reinterpret_cast<const float2*>(cb2 + nt * 8));
            }

            // S = Q K^T
            float cS[7][4];
            #pragma unroll
            for (int nt = 0; nt < 7; nt++) {
                const int krow = nt * 8 + (lane & 7);
                uint32_t koff = (uint32_t)krow * 256 + (((4 * h + ((lane >> 3) & 3)) ^ (krow & 7)) << 4);
                uint32_t bH[4], bL[4];
                ldmx4(bH, smem_base + RK_HI + koff);
                ldmx4(bL, smem_base + RK_LO + koff);
                float* c = cS[nt];
                c[0] = c[1] = c[2] = c[3] = 0.f;
                mma16816(c, qH[0], bH[0], bH[1]);
                mma16816(c, qH[0], bL[0], bL[1]);
                mma16816(c, qL[0], bH[0], bH[1]);
                mma16816(c, qH[1], bH[2], bH[3]);
                mma16816(c, qH[1], bL[2], bL[3]);
                mma16816(c, qL[1], bH[2], bH[3]);
            }

            // softmax in registers (no max pass; logits tiny)
            float s0 = 0.f, s1 = 0.f;
            #pragma unroll
            for (int nt = 0; nt < 7; nt++) {
                float a0 = __expf(fmaf(cS[nt][0], scale, cv1[nt].x));
                float a1 = __expf(fmaf(cS[nt][1], scale, cv1[nt].y));
                float a2 = __expf(fmaf(cS[nt][2], scale, cv2[nt].x));
                float a3 = __expf(fmaf(cS[nt][3], scale, cv2[nt].y));
                if (nt == 6) {
                    bool v0 = ((lane & 3) == 0);    // only j=48 valid
                    a0 = v0 ? a0 : 0.f;  a1 = 0.f;
                    a2 = v0 ? a2 : 0.f;  a3 = 0.f;
                }
                cS[nt][0] = a0; cS[nt][1] = a1; cS[nt][2] = a2; cS[nt][3] = a3;
                s0 += a0 + a1;  s1 += a2 + a3;
            }
            s0 += __shfl_xor_sync(0xffffffffu, s0, 1);
            s0 += __shfl_xor_sync(0xffffffffu, s0, 2);
            s1 += __shfl_xor_sync(0xffffffffu, s1, 1);
            s1 += __shfl_xor_sync(0xffffffffu, s1, 2);
            float i0 = 1.0f / s0, i1 = 1.0f / s1;

            // pack P A-fragments (hi/lo)
            uint32_t paH[4][4], paL[4][4];
            #pragma unroll
            for (int m = 0; m < 4; m++) {
                split2(cS[2 * m][0] * i0, cS[2 * m][1] * i0, paH[m][0], paL[m][0]);
                split2(cS[2 * m][2] * i1, cS[2 * m][3] * i1, paH[m][1], paL[m][1]);
                if (2 * m + 1 < 7) {
                    split2(cS[2 * m + 1][0] * i0, cS[2 * m + 1][1] * i0, paH[m][2], paL[m][2]);
                    split2(cS[2 * m + 1][2] * i1, cS[2 * m + 1][3] * i1, paH[m][3], paL[m][3]);
                } else {
                    paH[m][2] = paL[m][2] = 0u;
                    paH[m][3] = paL[m][3] = 0u;
                }
            }

            // O = P @ V (V row-major, transposed by ldmatrix.trans); epilogue -> A' imgs
            #pragma unroll
            for (int nt = 0; nt < 4; nt++) {
                const int cchunk = 4 * h + nt;
                const int ja = lane;            // j rows 0..31
                const int jb = lane + 32;       // j rows 32..63
                uint32_t voa = (uint32_t)ja * 256 + ((cchunk ^ (ja & 7)) << 4);
                uint32_t vob = (uint32_t)jb * 256 + ((cchunk ^ (jb & 7)) << 4);
                uint32_t vH0[4], vH1[4], vL0[4], vL1[4];
                ldmx4t(vH0, smem_base + RV_HI + voa);
                ldmx4t(vH1, smem_base + RV_HI + vob);
                ldmx4t(vL0, smem_base + RV_LO + voa);
                ldmx4t(vL1, smem_base + RV_LO + vob);

                float c[4] = {0.f, 0.f, 0.f, 0.f};
                mma16816(c, paH[0], vH0[0], vH0[1]);
                mma16816(c, paH[0], vL0[0], vL0[1]);
                mma16816(c, paL[0], vH0[0], vH0[1]);
                mma16816(c, paH[1], vH0[2], vH0[3]);
                mma16816(c, paH[1], vL0[2], vL0[3]);
                mma16816(c, paL[1], vH0[2], vH0[3]);
                mma16816(c, paH[2], vH1[0], vH1[1]);
                mma16816(c, paH[2], vL1[0], vL1[1]);
                mma16816(c, paL[2], vH1[0], vH1[1]);
                mma16816(c, paH[3], vH1[2], vH1[3]);
                mma16816(c, paH[3], vL1[2], vL1[3]);
                mma16816(c, paL[3], vH1[2], vH1[3]);

                uint32_t hp, lp;
                split2(c[0], c[1], hp, lp);
                uint32_t o1 = (uint32_t)r1 * 256 + ((cchunk ^ (r1 & 7)) << 4) + 4 * (lane & 3);
                *reinterpret_cast<uint32_t*>(smb + AP_HI + o1) = hp;
                *reinterpret_cast<uint32_t*>(smb + AP_LO + o1) = lp;
                split2(c[2], c[3], hp, lp);
                uint32_t o2 = (uint32_t)r2 * 256 + ((cchunk ^ (r2 & 7)) << 4) + 4 * (lane & 3);
                *reinterpret_cast<uint32_t*>(smb + AP_HI + o2) = hp;
                *reinterpret_cast<uint32_t*>(smb + AP_LO + o2) = lp;
            }
        }
    }
    __syncthreads();

    // ---- proj via mma, fragment-direct B; output -> global ----
    {
        uint32_t oH[8][4], oL[8][4];
        const int arow = mtb + (lane & 15);
        #pragma unroll
        for (int k = 0; k < 8; k++) {
            uint32_t off = (uint32_t)arow * 256 + (((2 * k + (lane >> 4)) ^ (arow & 7)) << 4);
            ldmx4(oH[k], smem_base + AP_HI + off);
            ldmx4(oL[k], smem_base + AP_LO + off);
        }
        float* outp = out_g + (size_t)blk * (NTOK * CDIM);
        #pragma unroll
        for (int nt8 = 0; nt8 < 8; nt8++) {
            const int ng4 = ng2 * 2 + (nt8 >> 2);
            const int nt4 = nt8 & 3;
            const uint4* fb = g_BprojF + (size_t)((ng4 * 4 + nt4) * 256) + lane;
            float c[4] = {0.f, 0.f, 0.f, 0.f};
            #pragma unroll
            for (int kt2 = 0; kt2 < 4; kt2++) {
                uint4 bhv = __ldg(fb + kt2 * 64);
                uint4 blv = __ldg(fb + kt2 * 64 + 32);
                mma16816(c, oH[2 * kt2],     bhv.x, bhv.y);
                mma16816(c, oH[2 * kt2],     blv.x, blv.y);
                mma16816(c, oL[2 * kt2],     bhv.x, bhv.y);
                mma16816(c, oH[2 * kt2 + 1], bhv.z, bhv.w);
                mma16816(c, oH[2 * kt2 + 1], blv.z, blv.w);
                mma16816(c, oL[2 * kt2 + 1], bhv.z, bhv.w);
            }
            const int n0 = ng2 * 64 + nt8 * 8;
            const int coll = n0 + 2 * (lane & 3);
            float2 bias = __ldg(reinterpret_cast<const float2*>(proj_b + coll));
            *reinterpret_cast<float2*>(outp + r1 * CDIM + coll) = make_float2(c[0] + bias.x, c[1] + bias.y);
            *reinterpret_cast<float2*>(outp + r2 * CDIM + coll) = make_float2(c[2] + bias.x, c[3] + bias.y);
        }
    }
}

extern "C" void kernel_launch(void* const* d_in, const int* in_sizes, int n_in,
                              void* d_out, int out_size) {
    const float* x      = (const float*)d_in[0];
    const float* mask   = (const float*)d_in[1];
    const float* qkv_w  = (const float*)d_in[2];
    const float* qkv_b  = (const float*)d_in[3];
    const float* proj_w = (const float*)d_in[4];
    const float* proj_b = (const float*)d_in[5];
    const float* rel    = (const float*)d_in[6];
    float* out = (float*)d_out;

    (void)in_sizes; (void)n_in; (void)out_size;

    cudaFuncSetAttribute(swin_mma_kernel,
                         cudaFuncAttributeMaxDynamicSharedMemorySize, SMEM_TOTAL_B);

    swin_prol_kernel<<<COMB_BLKS + 64, 256>>>(rel, mask, qkv_w, proj_w);
    swin_mma_kernel<<<NBLK, NTHREADS, SMEM_TOTAL_B>>>(x, qkv_b, proj_b, out);
}